// round 1
// baseline (speedup 1.0000x reference)
#include <cuda_runtime.h>
#include <cuda_bf16.h>
#include <cstdint>

// ---------------------------------------------------------------------------
// Decoder_84731114815924: contact-map decoder, fused tf32 tensor-core impl.
// B=4, N=256, D=32, H=512.
// Stage A : tmp[bi][c][h] = sum_a z[bi][a] * W1[(a*32+c)][h]      (SIMT GEMM)
// Main    : per (b,i,jtile): h1 = relu(z_j . tmp^T + b1)          (mma tf32)
//                            h2acc += h1 . W2                      (mma tf32)
//           epilogue: relu(+b2) . W3 + b3, mask, sigmoid.
// ---------------------------------------------------------------------------

#define BN      1024          // B*N
#define NJ      256
#define DD      32
#define HH      512
#define CH      16384         // 32*512  (c,h) flattened
#define BNN     262144        // B*N*N

__device__ float g_tmp[BN * CH];   // 64 MB scratch (allowed: device global)

__device__ __forceinline__ float to_tf32(float x) {
    uint32_t u;
    asm("cvt.rna.tf32.f32 %0, %1;" : "=r"(u) : "f"(x));
    return __uint_as_float(u);
}

#define MMA_TF32(D, A, B0, B1)                                              \
    asm volatile(                                                           \
        "mma.sync.aligned.m16n8k8.row.col.f32.tf32.tf32.f32 "               \
        "{%0,%1,%2,%3}, {%4,%5,%6,%7}, {%8,%9}, {%0,%1,%2,%3};\n"           \
        : "+f"(D[0]), "+f"(D[1]), "+f"(D[2]), "+f"(D[3])                    \
        : "r"(A[0]), "r"(A[1]), "r"(A[2]), "r"(A[3]), "r"(B0), "r"(B1))

// ---------------------------------------------------------------------------
// Stage A: tmp = Z(1024x32) @ Wflat(32x16384); Wflat[a][n] = W1[a*16384 + n]
// (n = c*512 + h, which is W1's native layout). Output tf32-rounded.
// grid (128, 16), block 256. CTA tile: 64 rows (bi) x 128 cols (n).
// ---------------------------------------------------------------------------
__global__ __launch_bounds__(256) void stage_a_kernel(
    const float* __restrict__ z, const float* __restrict__ W1)
{
    __shared__ float zt[64][33];
    __shared__ float wt[32][132];
    const int n0  = blockIdx.x * 128;
    const int bi0 = blockIdx.y * 64;
    const int tid = threadIdx.x;

    for (int idx = tid; idx < 64 * 32; idx += 256) {
        int r = idx >> 5, c = idx & 31;
        zt[r][c] = z[(bi0 + r) * 32 + c];
    }
    for (int idx = tid; idx < 32 * 128; idx += 256) {
        int r = idx >> 7, c = idx & 127;
        wt[r][c] = W1[r * CH + n0 + c];
    }
    __syncthreads();

    const int tm = tid & 15;   // 16 groups of 4 rows
    const int tn = tid >> 4;   // 16 groups of 8 cols

    float acc[4][8];
#pragma unroll
    for (int i = 0; i < 4; i++)
#pragma unroll
        for (int j = 0; j < 8; j++) acc[i][j] = 0.f;

#pragma unroll
    for (int k = 0; k < 32; k++) {
        float a[4], b[8];
#pragma unroll
        for (int i = 0; i < 4; i++) a[i] = zt[tm * 4 + i][k];
#pragma unroll
        for (int j = 0; j < 8; j++) b[j] = wt[k][tn * 8 + j];
#pragma unroll
        for (int i = 0; i < 4; i++)
#pragma unroll
            for (int j = 0; j < 8; j++) acc[i][j] = fmaf(a[i], b[j], acc[i][j]);
    }

#pragma unroll
    for (int i = 0; i < 4; i++) {
        const size_t base = (size_t)(bi0 + tm * 4 + i) * CH + n0 + tn * 8;
#pragma unroll
        for (int j = 0; j < 8; j++) g_tmp[base + j] = to_tf32(acc[i][j]);
    }
}

// ---------------------------------------------------------------------------
// Main fused kernel. grid 2048 = (b,i,jt), 512 threads, ~80 KB dyn smem.
// SMEM leading dims tuned so every mma-fragment LDS is bank-conflict-free.
// ---------------------------------------------------------------------------
#define LDZ 36
#define LDT 40
#define LDW 264
#define LDH 36
#define SMEM_FLOATS (128 * LDZ + 32 * LDT + 32 * LDW + 128 * LDH + 32 + 256 + 256 + 512)

__global__ __launch_bounds__(512, 1) void decoder_main_kernel(
    const float* __restrict__ z, const float* __restrict__ motif,
    const float* __restrict__ b1, const float* __restrict__ W2,
    const float* __restrict__ b2, const float* __restrict__ W3,
    const float* __restrict__ b3, float* __restrict__ out)
{
    extern __shared__ float sm[];
    float* zjs  = sm;                     // [128][LDZ]  z_j tile  (tf32)
    float* tmps = zjs + 128 * LDZ;        // [32][LDT]   tmp chunk [c][h]
    float* w2s  = tmps + 32 * LDT;        // [32][LDW]   W2 chunk  [h][k]
    float* h1s  = w2s + 32 * LDW;         // [128][LDH]  h1 chunk  [j][h]
    float* b1s  = h1s + 128 * LDH;        // [32]
    float* b2s  = b1s + 32;               // [256]
    float* w3s  = b2s + 256;              // [256]
    float* red  = w3s + 256;              // [128][4]

    const int cta = blockIdx.x;
    const int jt  = cta & 1;
    const int i   = (cta >> 1) & 255;
    const int b   = cta >> 9;
    const int bi  = b * 256 + i;
    const int j0  = jt * 128;

    const int tid  = threadIdx.x;
    const int w    = tid >> 5;
    const int lane = tid & 31;
    const int g    = lane >> 2;
    const int t    = lane & 3;

    // warp tiling
    const int m1 = (w & 7) * 16;        // GEMM1: j   m-tile
    const int n1 = (w >> 3) * 16;       // GEMM1: h   n-tile
    const int m2 = (w & 3) * 32;        // GEMM2: j   m-tile
    const int n2 = (w >> 2) * 64;       // GEMM2: k   n-tile

    if (tid < 256) { b2s[tid] = b2[tid]; w3s[tid] = W3[tid]; }
    for (int idx = tid; idx < 128 * 32; idx += 512) {
        int r = idx >> 5, c = idx & 31;
        zjs[r * LDZ + c] = to_tf32(z[(b * 256 + j0 + r) * 32 + c]);
    }

    float acc2[2][8][4];
#pragma unroll
    for (int mt = 0; mt < 2; mt++)
#pragma unroll
        for (int nt = 0; nt < 8; nt++)
#pragma unroll
            for (int r = 0; r < 4; r++) acc2[mt][nt][r] = 0.f;

    const float* tb = g_tmp + (size_t)bi * CH;

    for (int ch = 0; ch < 16; ch++) {
        const int h0 = ch * 32;

        // ---- stage loads -------------------------------------------------
        for (int idx = tid; idx < 1024; idx += 512) {          // tmp chunk
            int c = idx >> 5, hl = idx & 31;
            tmps[c * LDT + hl] = tb[c * 512 + h0 + hl];        // pre-rounded
        }
        {
            const float4* w2v = (const float4*)(W2 + h0 * 256);
            for (int idx = tid; idx < 2048; idx += 512) {      // W2 chunk
                float4 v = w2v[idx];
                v.x = to_tf32(v.x); v.y = to_tf32(v.y);
                v.z = to_tf32(v.z); v.w = to_tf32(v.w);
                int hl = idx >> 6, k4 = idx & 63;
                *(float4*)&w2s[hl * LDW + k4 * 4] = v;
            }
        }
        if (tid < 32) b1s[tid] = b1[h0 + tid];
        __syncthreads();

        // ---- GEMM1: h1[j][h] = relu(z_j . tmp^T + b1) --------------------
        float acc1[2][4];
#pragma unroll
        for (int nt = 0; nt < 2; nt++)
#pragma unroll
            for (int r = 0; r < 4; r++) acc1[nt][r] = 0.f;

#pragma unroll
        for (int ks = 0; ks < 4; ks++) {
            const int c0 = ks * 8;
            uint32_t a[4];
            a[0] = __float_as_uint(zjs[(m1 + g)     * LDZ + c0 + t]);
            a[1] = __float_as_uint(zjs[(m1 + g + 8) * LDZ + c0 + t]);
            a[2] = __float_as_uint(zjs[(m1 + g)     * LDZ + c0 + t + 4]);
            a[3] = __float_as_uint(zjs[(m1 + g + 8) * LDZ + c0 + t + 4]);
#pragma unroll
            for (int nt = 0; nt < 2; nt++) {
                uint32_t b0 = __float_as_uint(tmps[(c0 + t)     * LDT + n1 + nt * 8 + g]);
                uint32_t bb = __float_as_uint(tmps[(c0 + t + 4) * LDT + n1 + nt * 8 + g]);
                MMA_TF32(acc1[nt], a, b0, bb);
            }
        }
#pragma unroll
        for (int nt = 0; nt < 2; nt++)
#pragma unroll
            for (int r = 0; r < 4; r++) {
                int row = m1 + g + ((r >= 2) ? 8 : 0);
                int col = n1 + nt * 8 + t * 2 + (r & 1);
                float v = fmaxf(acc1[nt][r] + b1s[col], 0.f);
                h1s[row * LDH + col] = to_tf32(v);
            }
        __syncthreads();

        // ---- GEMM2: acc2 += h1 . W2 --------------------------------------
#pragma unroll
        for (int ks = 0; ks < 4; ks++) {
            const int c0 = ks * 8;
            uint32_t a[2][4];
#pragma unroll
            for (int mt = 0; mt < 2; mt++) {
                const int rb = m2 + mt * 16;
                a[mt][0] = __float_as_uint(h1s[(rb + g)     * LDH + c0 + t]);
                a[mt][1] = __float_as_uint(h1s[(rb + g + 8) * LDH + c0 + t]);
                a[mt][2] = __float_as_uint(h1s[(rb + g)     * LDH + c0 + t + 4]);
                a[mt][3] = __float_as_uint(h1s[(rb + g + 8) * LDH + c0 + t + 4]);
            }
#pragma unroll
            for (int nt = 0; nt < 8; nt++) {
                uint32_t b0 = __float_as_uint(w2s[(c0 + t)     * LDW + n2 + nt * 8 + g]);
                uint32_t bb = __float_as_uint(w2s[(c0 + t + 4) * LDW + n2 + nt * 8 + g]);
                MMA_TF32(acc2[0][nt], a[0], b0, bb);
                MMA_TF32(acc2[1][nt], a[1], b0, bb);
            }
        }
        __syncthreads();
    }

    // ---- epilogue: relu(+b2) . W3, cross-thread reduce, mask, sigmoid ----
    float psum[2][2] = {{0.f, 0.f}, {0.f, 0.f}};
#pragma unroll
    for (int mt = 0; mt < 2; mt++)
#pragma unroll
        for (int nt = 0; nt < 8; nt++)
#pragma unroll
            for (int r = 0; r < 4; r++) {
                int k = n2 + nt * 8 + t * 2 + (r & 1);
                float h2 = fmaxf(acc2[mt][nt][r] + b2s[k], 0.f);
                psum[mt][r >> 1] += h2 * w3s[k];
            }
#pragma unroll
    for (int mt = 0; mt < 2; mt++)
#pragma unroll
        for (int u = 0; u < 2; u++) {
            float v = psum[mt][u];
            v += __shfl_xor_sync(0xffffffffu, v, 1);
            v += __shfl_xor_sync(0xffffffffu, v, 2);
            psum[mt][u] = v;
        }
    if (t == 0) {
#pragma unroll
        for (int mt = 0; mt < 2; mt++)
#pragma unroll
            for (int u = 0; u < 2; u++) {
                int row = m2 + mt * 16 + g + u * 8;
                red[row * 4 + (w >> 2)] = psum[mt][u];
            }
    }
    __syncthreads();

    if (tid < 128) {
        float logit = red[tid * 4 + 0] + red[tid * 4 + 1] +
                      red[tid * 4 + 2] + red[tid * 4 + 3] + b3[0];
        float mask  = motif[b * 256 + i] * motif[b * 256 + j0 + tid];
        logit *= mask;
        float cmap = 1.f / (1.f + __expf(-logit));
        size_t base = ((size_t)b * 256 + i) * 256 + j0 + tid;
        out[base]        = cmap;
        out[BNN + base]  = logit;
    }
}

// ---------------------------------------------------------------------------
extern "C" void kernel_launch(void* const* d_in, const int* in_sizes, int n_in,
                              void* d_out, int out_size)
{
    const float* z     = (const float*)d_in[0];
    const float* motif = (const float*)d_in[1];
    // d_in[2] = residue_mask (unused by reference)
    const float* W1    = (const float*)d_in[3];
    const float* b1    = (const float*)d_in[4];
    const float* W2    = (const float*)d_in[5];
    const float* b2    = (const float*)d_in[6];
    const float* W3    = (const float*)d_in[7];
    const float* b3    = (const float*)d_in[8];
    float* out = (float*)d_out;

    (void)in_sizes; (void)n_in; (void)out_size;

    cudaFuncSetAttribute(decoder_main_kernel,
                         cudaFuncAttributeMaxDynamicSharedMemorySize,
                         SMEM_FLOATS * (int)sizeof(float));

    stage_a_kernel<<<dim3(128, 16), 256>>>(z, W1);
    decoder_main_kernel<<<2048, 512, SMEM_FLOATS * sizeof(float)>>>(
        z, motif, b1, W2, b2, W3, b3, out);
}

// round 4
// speedup vs baseline: 1.6211x; 1.6211x over previous
#include <cuda_runtime.h>
#include <cuda_bf16.h>
#include <cstdint>

// ---------------------------------------------------------------------------
// Decoder_84731114815924  (B=4, N=256, D=32, H=512)
// Round 2: 256-thr CTAs (2/SM), cp.async double-buffered chunk pipeline,
// fragment-major pre-packed operands (tf32 pre-rounded offline).
// ---------------------------------------------------------------------------

#define BN    1024
#define CH    16384
#define BNN   262144

__device__ float g_tmpf[BN * CH];        // 64 MB: GEMM1-B fragment-major tmp
__device__ float g_w2f[16 * 32 * 4 * 64];// 512 KB: GEMM2-B fragment-major W2
__device__ float g_zf[64 * 4 * 32 * 4];  // 128 KB: GEMM1-A fragment-major z

__device__ __forceinline__ float to_tf32(float x) {
    uint32_t u;
    asm("cvt.rna.tf32.f32 %0, %1;" : "=r"(u) : "f"(x));
    return __uint_as_float(u);
}

#define MMA_TF32(D, A, B0, B1)                                              \
    asm volatile(                                                           \
        "mma.sync.aligned.m16n8k8.row.col.f32.tf32.tf32.f32 "               \
        "{%0,%1,%2,%3}, {%4,%5,%6,%7}, {%8,%9}, {%0,%1,%2,%3};\n"           \
        : "+f"(D[0]), "+f"(D[1]), "+f"(D[2]), "+f"(D[3])                    \
        : "r"(A[0]), "r"(A[1]), "r"(A[2]), "r"(A[3]), "r"(B0), "r"(B1))

__device__ __forceinline__ void cp16(uint32_t s, const void* g) {
    asm volatile("cp.async.cg.shared.global [%0], [%1], 16;" :: "r"(s), "l"(g));
}
__device__ __forceinline__ void cp_commit() {
    asm volatile("cp.async.commit_group;");
}
__device__ __forceinline__ void cp_wait0() {
    asm volatile("cp.async.wait_group 0;");
}

// ---------------------------------------------------------------------------
// Stage A: tmp[bi][c][h] = sum_a z[bi][a] * W1[a*16384 + c*512 + h]
// stored directly in GEMM1-B fragment-major layout, tf32 rounded:
//   g_tmpf[((bi*16+ch)*16 + ntt*4 + ks)*64 + (g*4+t)*2 + e]
//     = tmp[bi][c = ks*8 + t + 4e][h = ch*32 + ntt*8 + g]
// ---------------------------------------------------------------------------
__global__ __launch_bounds__(256) void stage_a_kernel(
    const float* __restrict__ z, const float* __restrict__ W1)
{
    __shared__ float zt[64][33];
    __shared__ float wt[32][132];
    const int n0  = blockIdx.x * 128;
    const int bi0 = blockIdx.y * 64;
    const int tid = threadIdx.x;

    for (int idx = tid; idx < 64 * 32; idx += 256) {
        int r = idx >> 5, c = idx & 31;
        zt[r][c] = z[(bi0 + r) * 32 + c];
    }
    for (int idx = tid; idx < 32 * 128; idx += 256) {
        int r = idx >> 7, c = idx & 127;
        wt[r][c] = W1[r * CH + n0 + c];
    }
    __syncthreads();

    const int tm = tid & 15;
    const int tn = tid >> 4;

    float acc[4][8];
#pragma unroll
    for (int i = 0; i < 4; i++)
#pragma unroll
        for (int j = 0; j < 8; j++) acc[i][j] = 0.f;

#pragma unroll
    for (int k = 0; k < 32; k++) {
        float a[4], b[8];
#pragma unroll
        for (int i = 0; i < 4; i++) a[i] = zt[tm * 4 + i][k];
#pragma unroll
        for (int j = 0; j < 8; j++) b[j] = wt[k][tn * 8 + j];
#pragma unroll
        for (int i = 0; i < 4; i++)
#pragma unroll
            for (int j = 0; j < 8; j++) acc[i][j] = fmaf(a[i], b[j], acc[i][j]);
    }

    // fragment-major scatter store
    const int n_base = n0 + tn * 8;          // 8 consecutive n share one c
    const int c  = n_base >> 9;
    const int hb = n_base & 511;
    const int chk = hb >> 5;
    const int ntt = (hb >> 3) & 3;
    const int ks  = c >> 3;
    const int tt  = c & 7;
    const int t_  = tt & 3;
    const int e   = tt >> 2;
#pragma unroll
    for (int i = 0; i < 4; i++) {
        const int bi = bi0 + tm * 4 + i;
        const size_t base = (((size_t)bi * 16 + chk) * 16 + ntt * 4 + ks) * 64
                          + t_ * 2 + e;
#pragma unroll
        for (int j = 0; j < 8; j++)          // g = j
            g_tmpf[base + j * 8] = to_tf32(acc[i][j]);
    }
}

// ---------------------------------------------------------------------------
// Pack W2 into GEMM2-B fragment-major (tf32):
//   g_w2f[(((ch*32)+kt)*4 + ks)*64 + lane*2 + e] = W2[(ch*32+ks*8+t+4e)*256 + kt*8+g]
// ---------------------------------------------------------------------------
__global__ __launch_bounds__(256) void pack_w2_kernel(const float* __restrict__ W2)
{
    const int gid = blockIdx.x * 256 + threadIdx.x;   // 65536
    const int lane = gid & 31;
    const int ks   = (gid >> 5) & 3;
    const int kt   = (gid >> 7) & 31;
    const int chk  = gid >> 12;
    const int g = lane >> 2, t = lane & 3;
    const int h = chk * 32 + ks * 8 + t;
    const int k = kt * 8 + g;
    g_w2f[gid * 2 + 0] = to_tf32(W2[h * 256 + k]);
    g_w2f[gid * 2 + 1] = to_tf32(W2[(h + 4) * 256 + k]);
}

// ---------------------------------------------------------------------------
// Pack z into GEMM1-A fragment-major (tf32):
//   g_zf[(tile*4+ks)*128 + lane*4 + e]; tile = 16 global rows
// ---------------------------------------------------------------------------
__global__ __launch_bounds__(256) void pack_z_kernel(const float* __restrict__ z)
{
    const int gid = blockIdx.x * 256 + threadIdx.x;   // 8192
    const int lane = gid & 31;
    const int ks   = (gid >> 5) & 3;
    const int tile = gid >> 7;
    const int g = lane >> 2, t = lane & 3;
    const int r0 = tile * 16 + g;
    const int c0 = ks * 8 + t;
    g_zf[gid * 4 + 0] = to_tf32(z[r0 * 32 + c0]);
    g_zf[gid * 4 + 1] = to_tf32(z[(r0 + 8) * 32 + c0]);
    g_zf[gid * 4 + 2] = to_tf32(z[r0 * 32 + c0 + 4]);
    g_zf[gid * 4 + 3] = to_tf32(z[(r0 + 8) * 32 + c0 + 4]);
}

// ---------------------------------------------------------------------------
// Main fused kernel: grid 4096 = (b, i, jt of 4), 256 threads, 2 CTAs/SM.
// smem (floats):
//   zjs  [2048]   A-frags for 4 j row-tiles
//   tmps [2][1024]  GEMM1-B chunk (double buffered)
//   w2s  [2][8192]  GEMM2-B chunk (double buffered)
//   h1s  [64*36]
//   b1s[512] b2s[256] w3s[256] red[256]
// ---------------------------------------------------------------------------
#define SM_Z    0
#define SM_TMP  2048
#define SM_W2   4096
#define SM_H1   20480
#define SM_B1   22784
#define SM_B2   23296
#define SM_W3   23552
#define SM_RED  23808
#define SM_TOT  24064          // floats = 96256 bytes

__global__ __launch_bounds__(256, 2) void decoder_main_kernel(
    const float* __restrict__ motif,
    const float* __restrict__ b1, const float* __restrict__ b2,
    const float* __restrict__ W3, const float* __restrict__ b3,
    float* __restrict__ out)
{
    extern __shared__ float sm[];
    const uint32_t s_u32 = (uint32_t)__cvta_generic_to_shared(sm);

    const int cta = blockIdx.x;
    const int jt  = cta & 3;
    const int i   = (cta >> 2) & 255;
    const int b   = cta >> 10;
    const int bi  = b * 256 + i;
    const int j0  = jt * 64;

    const int tid  = threadIdx.x;
    const int w    = tid >> 5;
    const int lane = tid & 31;
    const int g    = lane >> 2;
    const int t    = lane & 3;

    // ---- prologue: async loads of zjs + chunk 0 -------------------------
    {
        const float4* zsrc = (const float4*)(g_zf + ((size_t)((b * 256 + j0) >> 4)) * 512);
        cp16(s_u32 + (SM_Z + tid * 4) * 4, zsrc + tid);
        cp16(s_u32 + (SM_Z + (tid + 256) * 4) * 4, zsrc + tid + 256);
        const float4* wsrc = (const float4*)(g_w2f);
#pragma unroll
        for (int r = 0; r < 8; r++)
            cp16(s_u32 + (SM_W2 + (tid + r * 256) * 4) * 4, wsrc + tid + r * 256);
        const float4* tsrc = (const float4*)(g_tmpf + (size_t)bi * CH);
        cp16(s_u32 + (SM_TMP + tid * 4) * 4, tsrc + tid);
        cp_commit();
    }
    // biases (regular loads, visible after first barrier)
    for (int idx = tid; idx < 1024; idx += 256) {
        if (idx < 512)       sm[SM_B1 + idx] = b1[idx];
        else if (idx < 768)  sm[SM_B2 + idx - 512] = b2[idx - 512];
        else                 sm[SM_W3 + idx - 768] = W3[idx - 768];
    }

    float acc2[2][8][4];
#pragma unroll
    for (int mt = 0; mt < 2; mt++)
#pragma unroll
        for (int nt = 0; nt < 8; nt++)
#pragma unroll
            for (int r = 0; r < 4; r++) acc2[mt][nt][r] = 0.f;

    // warp tiling
    const int rt  = w & 3;          // GEMM1: j row-tile (16 rows)
    const int nh  = w >> 2;         // GEMM1: h half (16 cols)
    const int m2  = (w & 1) * 32;   // GEMM2: j m-tile
    const int n2t = (w >> 1) * 8;   // GEMM2: k tile base (8 tiles of 8)

    int buf = 0;
    for (int chk = 0; chk < 16; chk++) {
        cp_wait0();
        __syncthreads();

        // prefetch next chunk into other buffer (overlaps GEMM1+GEMM2)
        if (chk < 15) {
            const int nb = buf ^ 1;
            const float4* wsrc = (const float4*)(g_w2f + (chk + 1) * 8192);
#pragma unroll
            for (int r = 0; r < 8; r++)
                cp16(s_u32 + (SM_W2 + nb * 8192 + (tid + r * 256) * 4) * 4,
                     wsrc + tid + r * 256);
            const float4* tsrc = (const float4*)(g_tmpf + (size_t)bi * CH + (chk + 1) * 1024);
            cp16(s_u32 + (SM_TMP + nb * 1024 + tid * 4) * 4, tsrc + tid);
            cp_commit();
        }

        const float* tb = sm + SM_TMP + buf * 1024;
        const float* wb = sm + SM_W2 + buf * 8192;

        // ---- GEMM1: h1 = relu(z_j . tmp^T + b1) -------------------------
        float acc1[2][4];
#pragma unroll
        for (int nt = 0; nt < 2; nt++)
#pragma unroll
            for (int r = 0; r < 4; r++) acc1[nt][r] = 0.f;

#pragma unroll
        for (int ks = 0; ks < 4; ks++) {
            float4 av = *(const float4*)&sm[SM_Z + ((rt * 4 + ks) * 32 + lane) * 4];
            uint32_t a[4] = { __float_as_uint(av.x), __float_as_uint(av.y),
                              __float_as_uint(av.z), __float_as_uint(av.w) };
#pragma unroll
            for (int nt = 0; nt < 2; nt++) {
                const int ntt = nh * 2 + nt;
                float2 bv = *(const float2*)&tb[((ntt * 4 + ks) * 32 + lane) * 2];
                MMA_TF32(acc1[nt], a, __float_as_uint(bv.x), __float_as_uint(bv.y));
            }
        }
#pragma unroll
        for (int nt = 0; nt < 2; nt++)
#pragma unroll
            for (int r = 0; r < 4; r++) {
                int row = rt * 16 + g + ((r >= 2) ? 8 : 0);
                int col = nh * 16 + nt * 8 + t * 2 + (r & 1);
                float v = fmaxf(acc1[nt][r] + sm[SM_B1 + chk * 32 + col], 0.f);
                sm[SM_H1 + row * 36 + col] = to_tf32(v);
            }
        __syncthreads();

        // ---- GEMM2: acc2 += h1 . W2chunk --------------------------------
#pragma unroll
        for (int ks = 0; ks < 4; ks++) {
            const int c0 = ks * 8;
            uint32_t a[2][4];
#pragma unroll
            for (int mt = 0; mt < 2; mt++) {
                const int rb = m2 + mt * 16;
                a[mt][0] = __float_as_uint(sm[SM_H1 + (rb + g) * 36 + c0 + t]);
                a[mt][1] = __float_as_uint(sm[SM_H1 + (rb + g + 8) * 36 + c0 + t]);
                a[mt][2] = __float_as_uint(sm[SM_H1 + (rb + g) * 36 + c0 + t + 4]);
                a[mt][3] = __float_as_uint(sm[SM_H1 + (rb + g + 8) * 36 + c0 + t + 4]);
            }
#pragma unroll
            for (int nt = 0; nt < 8; nt++) {
                const int kt = n2t + nt;
                float2 bv = *(const float2*)&wb[((kt * 4 + ks) * 32 + lane) * 2];
                uint32_t b0 = __float_as_uint(bv.x), bb = __float_as_uint(bv.y);
                MMA_TF32(acc2[0][nt], a[0], b0, bb);
                MMA_TF32(acc2[1][nt], a[1], b0, bb);
            }
        }
        buf ^= 1;
    }

    // ---- epilogue: relu(+b2) . W3, reduce, mask, sigmoid -----------------
    float psum[2][2] = {{0.f, 0.f}, {0.f, 0.f}};
#pragma unroll
    for (int mt = 0; mt < 2; mt++)
#pragma unroll
        for (int nt = 0; nt < 8; nt++)
#pragma unroll
            for (int r = 0; r < 4; r++) {
                int k = (n2t + nt) * 8 + t * 2 + (r & 1);
                float h2 = fmaxf(acc2[mt][nt][r] + sm[SM_B2 + k], 0.f);
                psum[mt][r >> 1] += h2 * sm[SM_W3 + k];
            }
#pragma unroll
    for (int mt = 0; mt < 2; mt++)
#pragma unroll
        for (int u = 0; u < 2; u++) {
            float v = psum[mt][u];
            v += __shfl_xor_sync(0xffffffffu, v, 1);
            v += __shfl_xor_sync(0xffffffffu, v, 2);
            psum[mt][u] = v;
        }
    __syncthreads();
    if (t == 0) {
#pragma unroll
        for (int mt = 0; mt < 2; mt++)
#pragma unroll
            for (int u = 0; u < 2; u++) {
                int row = m2 + mt * 16 + g + u * 8;
                sm[SM_RED + row * 4 + (w >> 1)] = psum[mt][u];
            }
    }
    __syncthreads();

    if (tid < 64) {
        const float* red = sm + SM_RED + tid * 4;
        float logit = red[0] + red[1] + red[2] + red[3] + b3[0];
        float mask  = motif[b * 256 + i] * motif[b * 256 + j0 + tid];
        logit *= mask;
        float cmap = 1.f / (1.f + __expf(-logit));
        size_t base = ((size_t)b * 256 + i) * 256 + j0 + tid;
        out[base]       = cmap;
        out[BNN + base] = logit;
    }
}

// ---------------------------------------------------------------------------
extern "C" void kernel_launch(void* const* d_in, const int* in_sizes, int n_in,
                              void* d_out, int out_size)
{
    const float* z     = (const float*)d_in[0];
    const float* motif = (const float*)d_in[1];
    const float* W1    = (const float*)d_in[3];
    const float* b1    = (const float*)d_in[4];
    const float* W2    = (const float*)d_in[5];
    const float* b2    = (const float*)d_in[6];
    const float* W3    = (const float*)d_in[7];
    const float* b3    = (const float*)d_in[8];
    float* out = (float*)d_out;

    (void)in_sizes; (void)n_in; (void)out_size;

    cudaFuncSetAttribute(decoder_main_kernel,
                         cudaFuncAttributeMaxDynamicSharedMemorySize,
                         SM_TOT * (int)sizeof(float));

    stage_a_kernel<<<dim3(128, 16), 256>>>(z, W1);
    pack_w2_kernel<<<256, 256>>>(W2);
    pack_z_kernel<<<32, 256>>>(z);
    decoder_main_kernel<<<4096, 256, SM_TOT * sizeof(float)>>>(
        motif, b1, b2, W3, b3, out);
}

// round 5
// speedup vs baseline: 1.6242x; 1.0019x over previous
#include <cuda_runtime.h>
#include <cuda_bf16.h>
#include <cstdint>

// ---------------------------------------------------------------------------
// Decoder_84731114815924  (B=4, N=256, D=32, H=512)
// Round 2: 256-thr CTAs (2/SM), cp.async double-buffered chunk pipeline,
// fragment-major pre-packed operands (tf32 pre-rounded offline).
// ---------------------------------------------------------------------------

#define BN    1024
#define CH    16384
#define BNN   262144

__device__ float g_tmpf[BN * CH];        // 64 MB: GEMM1-B fragment-major tmp
__device__ float g_w2f[16 * 32 * 4 * 64];// 512 KB: GEMM2-B fragment-major W2
__device__ float g_zf[64 * 4 * 32 * 4];  // 128 KB: GEMM1-A fragment-major z

__device__ __forceinline__ float to_tf32(float x) {
    uint32_t u;
    asm("cvt.rna.tf32.f32 %0, %1;" : "=r"(u) : "f"(x));
    return __uint_as_float(u);
}

#define MMA_TF32(D, A, B0, B1)                                              \
    asm volatile(                                                           \
        "mma.sync.aligned.m16n8k8.row.col.f32.tf32.tf32.f32 "               \
        "{%0,%1,%2,%3}, {%4,%5,%6,%7}, {%8,%9}, {%0,%1,%2,%3};\n"           \
        : "+f"(D[0]), "+f"(D[1]), "+f"(D[2]), "+f"(D[3])                    \
        : "r"(A[0]), "r"(A[1]), "r"(A[2]), "r"(A[3]), "r"(B0), "r"(B1))

__device__ __forceinline__ void cp16(uint32_t s, const void* g) {
    asm volatile("cp.async.cg.shared.global [%0], [%1], 16;" :: "r"(s), "l"(g));
}
__device__ __forceinline__ void cp_commit() {
    asm volatile("cp.async.commit_group;");
}
__device__ __forceinline__ void cp_wait0() {
    asm volatile("cp.async.wait_group 0;");
}

// ---------------------------------------------------------------------------
// Stage A: tmp[bi][c][h] = sum_a z[bi][a] * W1[a*16384 + c*512 + h]
// stored directly in GEMM1-B fragment-major layout, tf32 rounded:
//   g_tmpf[((bi*16+ch)*16 + ntt*4 + ks)*64 + (g*4+t)*2 + e]
//     = tmp[bi][c = ks*8 + t + 4e][h = ch*32 + ntt*8 + g]
// ---------------------------------------------------------------------------
__global__ __launch_bounds__(256) void stage_a_kernel(
    const float* __restrict__ z, const float* __restrict__ W1)
{
    __shared__ float zt[64][33];
    __shared__ float wt[32][132];
    const int n0  = blockIdx.x * 128;
    const int bi0 = blockIdx.y * 64;
    const int tid = threadIdx.x;

    for (int idx = tid; idx < 64 * 32; idx += 256) {
        int r = idx >> 5, c = idx & 31;
        zt[r][c] = z[(bi0 + r) * 32 + c];
    }
    for (int idx = tid; idx < 32 * 128; idx += 256) {
        int r = idx >> 7, c = idx & 127;
        wt[r][c] = W1[r * CH + n0 + c];
    }
    __syncthreads();

    const int tm = tid & 15;
    const int tn = tid >> 4;

    float acc[4][8];
#pragma unroll
    for (int i = 0; i < 4; i++)
#pragma unroll
        for (int j = 0; j < 8; j++) acc[i][j] = 0.f;

#pragma unroll
    for (int k = 0; k < 32; k++) {
        float a[4], b[8];
#pragma unroll
        for (int i = 0; i < 4; i++) a[i] = zt[tm * 4 + i][k];
#pragma unroll
        for (int j = 0; j < 8; j++) b[j] = wt[k][tn * 8 + j];
#pragma unroll
        for (int i = 0; i < 4; i++)
#pragma unroll
            for (int j = 0; j < 8; j++) acc[i][j] = fmaf(a[i], b[j], acc[i][j]);
    }

    // fragment-major scatter store
    const int n_base = n0 + tn * 8;          // 8 consecutive n share one c
    const int c  = n_base >> 9;
    const int hb = n_base & 511;
    const int chk = hb >> 5;
    const int ntt = (hb >> 3) & 3;
    const int ks  = c >> 3;
    const int tt  = c & 7;
    const int t_  = tt & 3;
    const int e   = tt >> 2;
#pragma unroll
    for (int i = 0; i < 4; i++) {
        const int bi = bi0 + tm * 4 + i;
        const size_t base = (((size_t)bi * 16 + chk) * 16 + ntt * 4 + ks) * 64
                          + t_ * 2 + e;
#pragma unroll
        for (int j = 0; j < 8; j++)          // g = j
            g_tmpf[base + j * 8] = to_tf32(acc[i][j]);
    }
}

// ---------------------------------------------------------------------------
// Pack W2 into GEMM2-B fragment-major (tf32):
//   g_w2f[(((ch*32)+kt)*4 + ks)*64 + lane*2 + e] = W2[(ch*32+ks*8+t+4e)*256 + kt*8+g]
// ---------------------------------------------------------------------------
__global__ __launch_bounds__(256) void pack_w2_kernel(const float* __restrict__ W2)
{
    const int gid = blockIdx.x * 256 + threadIdx.x;   // 65536
    const int lane = gid & 31;
    const int ks   = (gid >> 5) & 3;
    const int kt   = (gid >> 7) & 31;
    const int chk  = gid >> 12;
    const int g = lane >> 2, t = lane & 3;
    const int h = chk * 32 + ks * 8 + t;
    const int k = kt * 8 + g;
    g_w2f[gid * 2 + 0] = to_tf32(W2[h * 256 + k]);
    g_w2f[gid * 2 + 1] = to_tf32(W2[(h + 4) * 256 + k]);
}

// ---------------------------------------------------------------------------
// Pack z into GEMM1-A fragment-major (tf32):
//   g_zf[(tile*4+ks)*128 + lane*4 + e]; tile = 16 global rows
// ---------------------------------------------------------------------------
__global__ __launch_bounds__(256) void pack_z_kernel(const float* __restrict__ z)
{
    const int gid = blockIdx.x * 256 + threadIdx.x;   // 8192
    const int lane = gid & 31;
    const int ks   = (gid >> 5) & 3;
    const int tile = gid >> 7;
    const int g = lane >> 2, t = lane & 3;
    const int r0 = tile * 16 + g;
    const int c0 = ks * 8 + t;
    g_zf[gid * 4 + 0] = to_tf32(z[r0 * 32 + c0]);
    g_zf[gid * 4 + 1] = to_tf32(z[(r0 + 8) * 32 + c0]);
    g_zf[gid * 4 + 2] = to_tf32(z[r0 * 32 + c0 + 4]);
    g_zf[gid * 4 + 3] = to_tf32(z[(r0 + 8) * 32 + c0 + 4]);
}

// ---------------------------------------------------------------------------
// Main fused kernel: grid 4096 = (b, i, jt of 4), 256 threads, 2 CTAs/SM.
// smem (floats):
//   zjs  [2048]   A-frags for 4 j row-tiles
//   tmps [2][1024]  GEMM1-B chunk (double buffered)
//   w2s  [2][8192]  GEMM2-B chunk (double buffered)
//   h1s  [64*36]
//   b1s[512] b2s[256] w3s[256] red[256]
// ---------------------------------------------------------------------------
#define SM_Z    0
#define SM_TMP  2048
#define SM_W2   4096
#define SM_H1   20480
#define SM_B1   22784
#define SM_B2   23296
#define SM_W3   23552
#define SM_RED  23808
#define SM_TOT  24064          // floats = 96256 bytes

__global__ __launch_bounds__(256, 2) void decoder_main_kernel(
    const float* __restrict__ motif,
    const float* __restrict__ b1, const float* __restrict__ b2,
    const float* __restrict__ W3, const float* __restrict__ b3,
    float* __restrict__ out)
{
    extern __shared__ float sm[];
    const uint32_t s_u32 = (uint32_t)__cvta_generic_to_shared(sm);

    const int cta = blockIdx.x;
    const int jt  = cta & 3;
    const int i   = (cta >> 2) & 255;
    const int b   = cta >> 10;
    const int bi  = b * 256 + i;
    const int j0  = jt * 64;

    const int tid  = threadIdx.x;
    const int w    = tid >> 5;
    const int lane = tid & 31;
    const int g    = lane >> 2;
    const int t    = lane & 3;

    // ---- prologue: async loads of zjs + chunk 0 -------------------------
    {
        const float4* zsrc = (const float4*)(g_zf + ((size_t)((b * 256 + j0) >> 4)) * 512);
        cp16(s_u32 + (SM_Z + tid * 4) * 4, zsrc + tid);
        cp16(s_u32 + (SM_Z + (tid + 256) * 4) * 4, zsrc + tid + 256);
        const float4* wsrc = (const float4*)(g_w2f);
#pragma unroll
        for (int r = 0; r < 8; r++)
            cp16(s_u32 + (SM_W2 + (tid + r * 256) * 4) * 4, wsrc + tid + r * 256);
        const float4* tsrc = (const float4*)(g_tmpf + (size_t)bi * CH);
        cp16(s_u32 + (SM_TMP + tid * 4) * 4, tsrc + tid);
        cp_commit();
    }
    // biases (regular loads, visible after first barrier)
    for (int idx = tid; idx < 1024; idx += 256) {
        if (idx < 512)       sm[SM_B1 + idx] = b1[idx];
        else if (idx < 768)  sm[SM_B2 + idx - 512] = b2[idx - 512];
        else                 sm[SM_W3 + idx - 768] = W3[idx - 768];
    }

    float acc2[2][8][4];
#pragma unroll
    for (int mt = 0; mt < 2; mt++)
#pragma unroll
        for (int nt = 0; nt < 8; nt++)
#pragma unroll
            for (int r = 0; r < 4; r++) acc2[mt][nt][r] = 0.f;

    // warp tiling
    const int rt  = w & 3;          // GEMM1: j row-tile (16 rows)
    const int nh  = w >> 2;         // GEMM1: h half (16 cols)
    const int m2  = (w & 1) * 32;   // GEMM2: j m-tile
    const int n2t = (w >> 1) * 8;   // GEMM2: k tile base (8 tiles of 8)

    int buf = 0;
    for (int chk = 0; chk < 16; chk++) {
        cp_wait0();
        __syncthreads();

        // prefetch next chunk into other buffer (overlaps GEMM1+GEMM2)
        if (chk < 15) {
            const int nb = buf ^ 1;
            const float4* wsrc = (const float4*)(g_w2f + (chk + 1) * 8192);
#pragma unroll
            for (int r = 0; r < 8; r++)
                cp16(s_u32 + (SM_W2 + nb * 8192 + (tid + r * 256) * 4) * 4,
                     wsrc + tid + r * 256);
            const float4* tsrc = (const float4*)(g_tmpf + (size_t)bi * CH + (chk + 1) * 1024);
            cp16(s_u32 + (SM_TMP + nb * 1024 + tid * 4) * 4, tsrc + tid);
            cp_commit();
        }

        const float* tb = sm + SM_TMP + buf * 1024;
        const float* wb = sm + SM_W2 + buf * 8192;

        // ---- GEMM1: h1 = relu(z_j . tmp^T + b1) -------------------------
        float acc1[2][4];
#pragma unroll
        for (int nt = 0; nt < 2; nt++)
#pragma unroll
            for (int r = 0; r < 4; r++) acc1[nt][r] = 0.f;

#pragma unroll
        for (int ks = 0; ks < 4; ks++) {
            float4 av = *(const float4*)&sm[SM_Z + ((rt * 4 + ks) * 32 + lane) * 4];
            uint32_t a[4] = { __float_as_uint(av.x), __float_as_uint(av.y),
                              __float_as_uint(av.z), __float_as_uint(av.w) };
#pragma unroll
            for (int nt = 0; nt < 2; nt++) {
                const int ntt = nh * 2 + nt;
                float2 bv = *(const float2*)&tb[((ntt * 4 + ks) * 32 + lane) * 2];
                MMA_TF32(acc1[nt], a, __float_as_uint(bv.x), __float_as_uint(bv.y));
            }
        }
#pragma unroll
        for (int nt = 0; nt < 2; nt++)
#pragma unroll
            for (int r = 0; r < 4; r++) {
                int row = rt * 16 + g + ((r >= 2) ? 8 : 0);
                int col = nh * 16 + nt * 8 + t * 2 + (r & 1);
                float v = fmaxf(acc1[nt][r] + sm[SM_B1 + chk * 32 + col], 0.f);
                sm[SM_H1 + row * 36 + col] = to_tf32(v);
            }
        __syncthreads();

        // ---- GEMM2: acc2 += h1 . W2chunk --------------------------------
#pragma unroll
        for (int ks = 0; ks < 4; ks++) {
            const int c0 = ks * 8;
            uint32_t a[2][4];
#pragma unroll
            for (int mt = 0; mt < 2; mt++) {
                const int rb = m2 + mt * 16;
                a[mt][0] = __float_as_uint(sm[SM_H1 + (rb + g) * 36 + c0 + t]);
                a[mt][1] = __float_as_uint(sm[SM_H1 + (rb + g + 8) * 36 + c0 + t]);
                a[mt][2] = __float_as_uint(sm[SM_H1 + (rb + g) * 36 + c0 + t + 4]);
                a[mt][3] = __float_as_uint(sm[SM_H1 + (rb + g + 8) * 36 + c0 + t + 4]);
            }
#pragma unroll
            for (int nt = 0; nt < 8; nt++) {
                const int kt = n2t + nt;
                float2 bv = *(const float2*)&wb[((kt * 4 + ks) * 32 + lane) * 2];
                uint32_t b0 = __float_as_uint(bv.x), bb = __float_as_uint(bv.y);
                MMA_TF32(acc2[0][nt], a[0], b0, bb);
                MMA_TF32(acc2[1][nt], a[1], b0, bb);
            }
        }
        buf ^= 1;
    }

    // ---- epilogue: relu(+b2) . W3, reduce, mask, sigmoid -----------------
    float psum[2][2] = {{0.f, 0.f}, {0.f, 0.f}};
#pragma unroll
    for (int mt = 0; mt < 2; mt++)
#pragma unroll
        for (int nt = 0; nt < 8; nt++)
#pragma unroll
            for (int r = 0; r < 4; r++) {
                int k = (n2t + nt) * 8 + t * 2 + (r & 1);
                float h2 = fmaxf(acc2[mt][nt][r] + sm[SM_B2 + k], 0.f);
                psum[mt][r >> 1] += h2 * sm[SM_W3 + k];
            }
#pragma unroll
    for (int mt = 0; mt < 2; mt++)
#pragma unroll
        for (int u = 0; u < 2; u++) {
            float v = psum[mt][u];
            v += __shfl_xor_sync(0xffffffffu, v, 1);
            v += __shfl_xor_sync(0xffffffffu, v, 2);
            psum[mt][u] = v;
        }
    __syncthreads();
    if (t == 0) {
#pragma unroll
        for (int mt = 0; mt < 2; mt++)
#pragma unroll
            for (int u = 0; u < 2; u++) {
                int row = m2 + mt * 16 + g + u * 8;
                sm[SM_RED + row * 4 + (w >> 1)] = psum[mt][u];
            }
    }
    __syncthreads();

    if (tid < 64) {
        const float* red = sm + SM_RED + tid * 4;
        float logit = red[0] + red[1] + red[2] + red[3] + b3[0];
        float mask  = motif[b * 256 + i] * motif[b * 256 + j0 + tid];
        logit *= mask;
        float cmap = 1.f / (1.f + __expf(-logit));
        size_t base = ((size_t)b * 256 + i) * 256 + j0 + tid;
        out[base]       = cmap;
        out[BNN + base] = logit;
    }
}

// ---------------------------------------------------------------------------
extern "C" void kernel_launch(void* const* d_in, const int* in_sizes, int n_in,
                              void* d_out, int out_size)
{
    const float* z     = (const float*)d_in[0];
    const float* motif = (const float*)d_in[1];
    const float* W1    = (const float*)d_in[3];
    const float* b1    = (const float*)d_in[4];
    const float* W2    = (const float*)d_in[5];
    const float* b2    = (const float*)d_in[6];
    const float* W3    = (const float*)d_in[7];
    const float* b3    = (const float*)d_in[8];
    float* out = (float*)d_out;

    (void)in_sizes; (void)n_in; (void)out_size;

    cudaFuncSetAttribute(decoder_main_kernel,
                         cudaFuncAttributeMaxDynamicSharedMemorySize,
                         SM_TOT * (int)sizeof(float));

    stage_a_kernel<<<dim3(128, 16), 256>>>(z, W1);
    pack_w2_kernel<<<256, 256>>>(W2);
    pack_z_kernel<<<32, 256>>>(z);
    decoder_main_kernel<<<4096, 256, SM_TOT * sizeof(float)>>>(
        motif, b1, b2, W3, b3, out);
}

// round 8
// speedup vs baseline: 1.7101x; 1.0529x over previous
#include <cuda_runtime.h>
#include <cuda_bf16.h>
#include <cstdint>

// ---------------------------------------------------------------------------
// Decoder_84731114815924  (B=4, N=256, D=32, H=512)
// mma.sync tf32 path (tcgen05 unavailable: harness ptxas target is sm_103).
// R6: stage-A vectorized fragment stores + fragment-major h1 (LDS.128 A-frags).
// ---------------------------------------------------------------------------

#define BN    1024
#define CH    16384
#define BNN   262144

__device__ float g_tmpf[BN * CH];        // 64 MB: GEMM1-B fragment-major tmp
__device__ float g_w2f[16 * 32 * 4 * 64];// 512 KB: GEMM2-B fragment-major W2
__device__ float g_zf[64 * 4 * 32 * 4];  // 128 KB: GEMM1-A fragment-major z

__device__ __forceinline__ float to_tf32(float x) {
    uint32_t u;
    asm("cvt.rna.tf32.f32 %0, %1;" : "=r"(u) : "f"(x));
    return __uint_as_float(u);
}

#define MMA_TF32(D, A, B0, B1)                                              \
    asm volatile(                                                           \
        "mma.sync.aligned.m16n8k8.row.col.f32.tf32.tf32.f32 "               \
        "{%0,%1,%2,%3}, {%4,%5,%6,%7}, {%8,%9}, {%0,%1,%2,%3};\n"           \
        : "+f"(D[0]), "+f"(D[1]), "+f"(D[2]), "+f"(D[3])                    \
        : "r"(A[0]), "r"(A[1]), "r"(A[2]), "r"(A[3]), "r"(B0), "r"(B1))

__device__ __forceinline__ void cp16(uint32_t s, const void* g) {
    asm volatile("cp.async.cg.shared.global [%0], [%1], 16;" :: "r"(s), "l"(g));
}
__device__ __forceinline__ void cp_commit() {
    asm volatile("cp.async.commit_group;");
}
__device__ __forceinline__ void cp_wait0() {
    asm volatile("cp.async.wait_group 0;");
}

// ---------------------------------------------------------------------------
// Stage A: tmp[bi][c][h] = sum_a z[bi][a] * W1[a*16384 + c*512 + h], written
// straight into GEMM1-B fragment-major layout with float4 stores:
//   g_tmpf[((bi*16+chk)*16 + ntt*4 + ks)*64 + g*8 + t*2 + e]
//     = tmp[bi][c = ks*8 + t + 4e][h = chk*32 + ntt*8 + g]
// Block: 64 bi x 8 c (ks = oct) x 16 h. Thread: 4 bi x 8 c for one h.
// Per (bi): 8 consecutive fragment floats = the 8 c's -> two float4 stores.
// ---------------------------------------------------------------------------
__global__ __launch_bounds__(256) void stage_a_kernel(
    const float* __restrict__ z, const float* __restrict__ W1)
{
    __shared__ float zt[64][33];
    __shared__ float wt[32][132];
    const int oct = blockIdx.x & 3;        // ks  (c0 = oct*8)
    const int hg  = blockIdx.x >> 2;       // h0 = hg*16
    const int bi0 = blockIdx.y * 64;
    const int c0  = oct * 8, h0 = hg * 16;
    const int tid = threadIdx.x;

    for (int idx = tid; idx < 64 * 32; idx += 256) {
        int r = idx >> 5, a = idx & 31;
        zt[r][a] = z[(bi0 + r) * 32 + a];
    }
    for (int idx = tid; idx < 32 * 128; idx += 256) {
        int a = idx >> 7, col = idx & 127;
        int ci = col >> 4, hi = col & 15;
        wt[a][col] = W1[a * CH + (c0 + ci) * 512 + h0 + hi];
    }
    __syncthreads();

    const int tm = tid >> 4;   // 16 groups of 4 bi
    const int tn = tid & 15;   // h within 16

    float acc[4][8];
#pragma unroll
    for (int i = 0; i < 4; i++)
#pragma unroll
        for (int j = 0; j < 8; j++) acc[i][j] = 0.f;

#pragma unroll
    for (int k = 0; k < 32; k++) {
        float a[4], bb[8];
#pragma unroll
        for (int i = 0; i < 4; i++) a[i] = zt[tm * 4 + i][k];
#pragma unroll
        for (int j = 0; j < 8; j++) bb[j] = wt[k][j * 16 + tn];
#pragma unroll
        for (int i = 0; i < 4; i++)
#pragma unroll
            for (int j = 0; j < 8; j++) acc[i][j] = fmaf(a[i], bb[j], acc[i][j]);
    }

    const int h   = h0 + tn;
    const int chk = h >> 5;
    const int ntt = (h >> 3) & 3;
    const int g   = h & 7;
#pragma unroll
    for (int i = 0; i < 4; i++) {
        const int bi = bi0 + tm * 4 + i;
        const size_t base = (((size_t)bi * 16 + chk) * 16 + ntt * 4 + oct) * 64 + g * 8;
        // slot order t*2+e: c = oct*8 + t + 4e  ->  {0,4,1,5} then {2,6,3,7}
        float4 f0 = { to_tf32(acc[i][0]), to_tf32(acc[i][4]),
                      to_tf32(acc[i][1]), to_tf32(acc[i][5]) };
        float4 f1 = { to_tf32(acc[i][2]), to_tf32(acc[i][6]),
                      to_tf32(acc[i][3]), to_tf32(acc[i][7]) };
        *(float4*)&g_tmpf[base]     = f0;
        *(float4*)&g_tmpf[base + 4] = f1;
    }
}

// ---------------------------------------------------------------------------
// Pack W2 into GEMM2-B fragment-major (tf32):
//   g_w2f[(((ch*32)+kt)*4 + ks)*64 + lane*2 + e] = W2[(ch*32+ks*8+t+4e)*256 + kt*8+g]
// ---------------------------------------------------------------------------
__global__ __launch_bounds__(256) void pack_w2_kernel(const float* __restrict__ W2)
{
    const int gid = blockIdx.x * 256 + threadIdx.x;   // 65536
    const int lane = gid & 31;
    const int ks   = (gid >> 5) & 3;
    const int kt   = (gid >> 7) & 31;
    const int chk  = gid >> 12;
    const int g = lane >> 2, t = lane & 3;
    const int h = chk * 32 + ks * 8 + t;
    const int k = kt * 8 + g;
    g_w2f[gid * 2 + 0] = to_tf32(W2[h * 256 + k]);
    g_w2f[gid * 2 + 1] = to_tf32(W2[(h + 4) * 256 + k]);
}

// ---------------------------------------------------------------------------
// Pack z into GEMM1-A fragment-major (tf32):
//   g_zf[(tile*4+ks)*128 + lane*4 + e]; tile = 16 global rows
// ---------------------------------------------------------------------------
__global__ __launch_bounds__(256) void pack_z_kernel(const float* __restrict__ z)
{
    const int gid = blockIdx.x * 256 + threadIdx.x;   // 8192
    const int lane = gid & 31;
    const int ks   = (gid >> 5) & 3;
    const int tile = gid >> 7;
    const int g = lane >> 2, t = lane & 3;
    const int r0 = tile * 16 + g;
    const int c0 = ks * 8 + t;
    g_zf[gid * 4 + 0] = to_tf32(z[r0 * 32 + c0]);
    g_zf[gid * 4 + 1] = to_tf32(z[(r0 + 8) * 32 + c0]);
    g_zf[gid * 4 + 2] = to_tf32(z[r0 * 32 + c0 + 4]);
    g_zf[gid * 4 + 3] = to_tf32(z[(r0 + 8) * 32 + c0 + 4]);
}

// ---------------------------------------------------------------------------
// Main fused kernel: grid 4096 = (b, i, jt of 4), 256 threads, 2 CTAs/SM.
// h1 kept fragment-major in smem:
//   h1f[((rt*4 + ks)*32 + g*4 + t)*4 + e*2 + half]
//     = h1[j = rt*16 + half*8 + g][c = ks*8 + t + 4e]
// so each GEMM2 A-fragment is one LDS.128.
// ---------------------------------------------------------------------------
#define SM_Z    0
#define SM_TMP  2048
#define SM_W2   4096
#define SM_H1   20480
#define SM_B1   22528
#define SM_B2   23040
#define SM_W3   23296
#define SM_RED  23552
#define SM_TOT  23808          // floats = 95232 bytes

__global__ __launch_bounds__(256, 2) void decoder_main_kernel(
    const float* __restrict__ motif,
    const float* __restrict__ b1, const float* __restrict__ b2,
    const float* __restrict__ W3, const float* __restrict__ b3,
    float* __restrict__ out)
{
    extern __shared__ float sm[];
    const uint32_t s_u32 = (uint32_t)__cvta_generic_to_shared(sm);

    const int cta = blockIdx.x;
    const int jt  = cta & 3;
    const int i   = (cta >> 2) & 255;
    const int b   = cta >> 10;
    const int bi  = b * 256 + i;
    const int j0  = jt * 64;

    const int tid  = threadIdx.x;
    const int w    = tid >> 5;
    const int lane = tid & 31;
    const int g    = lane >> 2;
    const int t    = lane & 3;

    // ---- prologue: async loads of zjs + chunk 0 -------------------------
    {
        const float4* zsrc = (const float4*)(g_zf + ((size_t)((b * 256 + j0) >> 4)) * 512);
        cp16(s_u32 + (SM_Z + tid * 4) * 4, zsrc + tid);
        cp16(s_u32 + (SM_Z + (tid + 256) * 4) * 4, zsrc + tid + 256);
        const float4* wsrc = (const float4*)(g_w2f);
#pragma unroll
        for (int r = 0; r < 8; r++)
            cp16(s_u32 + (SM_W2 + (tid + r * 256) * 4) * 4, wsrc + tid + r * 256);
        const float4* tsrc = (const float4*)(g_tmpf + (size_t)bi * CH);
        cp16(s_u32 + (SM_TMP + tid * 4) * 4, tsrc + tid);
        cp_commit();
    }
    for (int idx = tid; idx < 1024; idx += 256) {
        if (idx < 512)       sm[SM_B1 + idx] = b1[idx];
        else if (idx < 768)  sm[SM_B2 + idx - 512] = b2[idx - 512];
        else                 sm[SM_W3 + idx - 768] = W3[idx - 768];
    }

    float acc2[2][8][4];
#pragma unroll
    for (int mt = 0; mt < 2; mt++)
#pragma unroll
        for (int nt = 0; nt < 8; nt++)
#pragma unroll
            for (int r = 0; r < 4; r++) acc2[mt][nt][r] = 0.f;

    // warp tiling
    const int rt  = w & 3;          // GEMM1: j row-tile (16 rows)
    const int nh  = w >> 2;         // GEMM1: h half (16 cols)
    const int m2  = (w & 1) * 32;   // GEMM2: j m-tile base
    const int rt2 = (w & 1) * 2;    // GEMM2: h1f row-tile base
    const int n2t = (w >> 1) * 8;   // GEMM2: k tile base (8 tiles of 8)

    int buf = 0;
    for (int chk = 0; chk < 16; chk++) {
        cp_wait0();
        __syncthreads();

        // prefetch next chunk into other buffer (overlaps GEMM1+GEMM2)
        if (chk < 15) {
            const int nb = buf ^ 1;
            const float4* wsrc = (const float4*)(g_w2f + (chk + 1) * 8192);
#pragma unroll
            for (int r = 0; r < 8; r++)
                cp16(s_u32 + (SM_W2 + nb * 8192 + (tid + r * 256) * 4) * 4,
                     wsrc + tid + r * 256);
            const float4* tsrc = (const float4*)(g_tmpf + (size_t)bi * CH + (chk + 1) * 1024);
            cp16(s_u32 + (SM_TMP + nb * 1024 + tid * 4) * 4, tsrc + tid);
            cp_commit();
        }

        const float* tb = sm + SM_TMP + buf * 1024;
        const float* wb = sm + SM_W2 + buf * 8192;

        // ---- GEMM1: h1 = relu(z_j . tmp^T + b1) -------------------------
        float acc1[2][4];
#pragma unroll
        for (int nt = 0; nt < 2; nt++)
#pragma unroll
            for (int r = 0; r < 4; r++) acc1[nt][r] = 0.f;

#pragma unroll
        for (int ks = 0; ks < 4; ks++) {
            float4 av = *(const float4*)&sm[SM_Z + ((rt * 4 + ks) * 32 + lane) * 4];
            uint32_t a[4] = { __float_as_uint(av.x), __float_as_uint(av.y),
                              __float_as_uint(av.z), __float_as_uint(av.w) };
#pragma unroll
            for (int nt = 0; nt < 2; nt++) {
                const int ntt = nh * 2 + nt;
                float2 bv = *(const float2*)&tb[((ntt * 4 + ks) * 32 + lane) * 2];
                MMA_TF32(acc1[nt], a, __float_as_uint(bv.x), __float_as_uint(bv.y));
            }
        }
        // write h1 fragment-major
#pragma unroll
        for (int nt = 0; nt < 2; nt++)
#pragma unroll
            for (int r = 0; r < 4; r++) {
                int col  = nh * 16 + nt * 8 + t * 2 + (r & 1);   // h within chunk
                int ks2  = col >> 3;
                int cc   = col & 7;
                int e    = cc >> 2, t2 = cc & 3;
                int half = (r >> 1);
                float v = fmaxf(acc1[nt][r] + sm[SM_B1 + chk * 32 + col], 0.f);
                sm[SM_H1 + ((rt * 4 + ks2) * 32 + g * 4 + t2) * 4 + e * 2 + half]
                    = to_tf32(v);
            }
        __syncthreads();

        // ---- GEMM2: acc2 += h1 . W2chunk --------------------------------
#pragma unroll
        for (int ks = 0; ks < 4; ks++) {
            uint32_t a[2][4];
#pragma unroll
            for (int mt = 0; mt < 2; mt++) {
                float4 av = *(const float4*)&sm[SM_H1 + ((rt2 + mt) * 4 + ks) * 128 + lane * 4];
                a[mt][0] = __float_as_uint(av.x);
                a[mt][1] = __float_as_uint(av.y);
                a[mt][2] = __float_as_uint(av.z);
                a[mt][3] = __float_as_uint(av.w);
            }
#pragma unroll
            for (int nt = 0; nt < 8; nt++) {
                const int kt = n2t + nt;
                float2 bv = *(const float2*)&wb[((kt * 4 + ks) * 32 + lane) * 2];
                uint32_t b0 = __float_as_uint(bv.x), bb = __float_as_uint(bv.y);
                MMA_TF32(acc2[0][nt], a[0], b0, bb);
                MMA_TF32(acc2[1][nt], a[1], b0, bb);
            }
        }
        buf ^= 1;
    }

    // ---- epilogue: relu(+b2) . W3, reduce, mask, sigmoid -----------------
    float psum[2][2] = {{0.f, 0.f}, {0.f, 0.f}};
#pragma unroll
    for (int mt = 0; mt < 2; mt++)
#pragma unroll
        for (int nt = 0; nt < 8; nt++)
#pragma unroll
            for (int r = 0; r < 4; r++) {
                int k = (n2t + nt) * 8 + t * 2 + (r & 1);
                float h2 = fmaxf(acc2[mt][nt][r] + sm[SM_B2 + k], 0.f);
                psum[mt][r >> 1] += h2 * sm[SM_W3 + k];
            }
#pragma unroll
    for (int mt = 0; mt < 2; mt++)
#pragma unroll
        for (int u = 0; u < 2; u++) {
            float v = psum[mt][u];
            v += __shfl_xor_sync(0xffffffffu, v, 1);
            v += __shfl_xor_sync(0xffffffffu, v, 2);
            psum[mt][u] = v;
        }
    __syncthreads();
    if (t == 0) {
#pragma unroll
        for (int mt = 0; mt < 2; mt++)
#pragma unroll
            for (int u = 0; u < 2; u++) {
                int row = m2 + mt * 16 + g + u * 8;
                sm[SM_RED + row * 4 + (w >> 1)] = psum[mt][u];
            }
    }
    __syncthreads();

    if (tid < 64) {
        const float* red = sm + SM_RED + tid * 4;
        float logit = red[0] + red[1] + red[2] + red[3] + b3[0];
        float mask  = motif[b * 256 + i] * motif[b * 256 + j0 + tid];
        logit *= mask;
        float cmap = 1.f / (1.f + __expf(-logit));
        size_t base = ((size_t)b * 256 + i) * 256 + j0 + tid;
        out[base]       = cmap;
        out[BNN + base] = logit;
    }
}

// ---------------------------------------------------------------------------
extern "C" void kernel_launch(void* const* d_in, const int* in_sizes, int n_in,
                              void* d_out, int out_size)
{
    const float* z     = (const float*)d_in[0];
    const float* motif = (const float*)d_in[1];
    const float* W1    = (const float*)d_in[3];
    const float* b1    = (const float*)d_in[4];
    const float* W2    = (const float*)d_in[5];
    const float* b2    = (const float*)d_in[6];
    const float* W3    = (const float*)d_in[7];
    const float* b3    = (const float*)d_in[8];
    float* out = (float*)d_out;

    (void)in_sizes; (void)n_in; (void)out_size;

    cudaFuncSetAttribute(decoder_main_kernel,
                         cudaFuncAttributeMaxDynamicSharedMemorySize,
                         SM_TOT * (int)sizeof(float));

    stage_a_kernel<<<dim3(128, 16), 256>>>(z, W1);
    pack_w2_kernel<<<256, 256>>>(W2);
    pack_z_kernel<<<32, 256>>>(z);
    decoder_main_kernel<<<4096, 256, SM_TOT * sizeof(float)>>>(
        motif, b1, b2, W3, b3, out);
}

// round 9
// speedup vs baseline: 1.7104x; 1.0002x over previous
#include <cuda_runtime.h>
#include <cuda_bf16.h>
#include <cstdint>

// ---------------------------------------------------------------------------
// Decoder_84731114815924  (B=4, N=256, D=32, H=512)
// mma.sync tf32 path. R9: warp-owns-j restructure — GEMM1 C-fragments are
// converted to GEMM2 A-fragments via register shuffles (no h1 smem roundtrip,
// one barrier per chunk).
// ---------------------------------------------------------------------------

#define BN    1024
#define CH    16384
#define BNN   262144

__device__ float g_tmpf[BN * CH];        // 64 MB: GEMM1-B fragment-major tmp
__device__ float g_w2f[16 * 32 * 4 * 64];// 512 KB: GEMM2-B fragment-major W2
__device__ float g_zf[64 * 4 * 32 * 4];  // 128 KB: GEMM1-A fragment-major z

__device__ __forceinline__ float to_tf32(float x) {
    uint32_t u;
    asm("cvt.rna.tf32.f32 %0, %1;" : "=r"(u) : "f"(x));
    return __uint_as_float(u);
}

#define MMA_TF32(D, A, B0, B1)                                              \
    asm volatile(                                                           \
        "mma.sync.aligned.m16n8k8.row.col.f32.tf32.tf32.f32 "               \
        "{%0,%1,%2,%3}, {%4,%5,%6,%7}, {%8,%9}, {%0,%1,%2,%3};\n"           \
        : "+f"(D[0]), "+f"(D[1]), "+f"(D[2]), "+f"(D[3])                    \
        : "r"(A[0]), "r"(A[1]), "r"(A[2]), "r"(A[3]), "r"(B0), "r"(B1))

__device__ __forceinline__ void cp16(uint32_t s, const void* g) {
    asm volatile("cp.async.cg.shared.global [%0], [%1], 16;" :: "r"(s), "l"(g));
}
__device__ __forceinline__ void cp_commit() {
    asm volatile("cp.async.commit_group;");
}
__device__ __forceinline__ void cp_wait0() {
    asm volatile("cp.async.wait_group 0;");
}

// ---------------------------------------------------------------------------
// Stage A: tmp[bi][c][h] = sum_a z[bi][a] * W1[a*16384 + c*512 + h], written
// straight into GEMM1-B fragment-major layout with float4 stores:
//   g_tmpf[((bi*16+chk)*16 + ntt*4 + ks)*64 + g*8 + t*2 + e]
//     = tmp[bi][c = ks*8 + t + 4e][h = chk*32 + ntt*8 + g]
// ---------------------------------------------------------------------------
__global__ __launch_bounds__(256) void stage_a_kernel(
    const float* __restrict__ z, const float* __restrict__ W1)
{
    __shared__ float zt[64][33];
    __shared__ float wt[32][132];
    const int oct = blockIdx.x & 3;        // ks  (c0 = oct*8)
    const int hg  = blockIdx.x >> 2;       // h0 = hg*16
    const int bi0 = blockIdx.y * 64;
    const int c0  = oct * 8, h0 = hg * 16;
    const int tid = threadIdx.x;

    for (int idx = tid; idx < 64 * 32; idx += 256) {
        int r = idx >> 5, a = idx & 31;
        zt[r][a] = z[(bi0 + r) * 32 + a];
    }
    for (int idx = tid; idx < 32 * 128; idx += 256) {
        int a = idx >> 7, col = idx & 127;
        int ci = col >> 4, hi = col & 15;
        wt[a][col] = W1[a * CH + (c0 + ci) * 512 + h0 + hi];
    }
    __syncthreads();

    const int tm = tid >> 4;   // 16 groups of 4 bi
    const int tn = tid & 15;   // h within 16

    float acc[4][8];
#pragma unroll
    for (int i = 0; i < 4; i++)
#pragma unroll
        for (int j = 0; j < 8; j++) acc[i][j] = 0.f;

#pragma unroll
    for (int k = 0; k < 32; k++) {
        float a[4], bb[8];
#pragma unroll
        for (int i = 0; i < 4; i++) a[i] = zt[tm * 4 + i][k];
#pragma unroll
        for (int j = 0; j < 8; j++) bb[j] = wt[k][j * 16 + tn];
#pragma unroll
        for (int i = 0; i < 4; i++)
#pragma unroll
            for (int j = 0; j < 8; j++) acc[i][j] = fmaf(a[i], bb[j], acc[i][j]);
    }

    const int h   = h0 + tn;
    const int chk = h >> 5;
    const int ntt = (h >> 3) & 3;
    const int g   = h & 7;
#pragma unroll
    for (int i = 0; i < 4; i++) {
        const int bi = bi0 + tm * 4 + i;
        const size_t base = (((size_t)bi * 16 + chk) * 16 + ntt * 4 + oct) * 64 + g * 8;
        // slot order t*2+e: c = oct*8 + t + 4e  ->  {0,4,1,5} then {2,6,3,7}
        float4 f0 = { to_tf32(acc[i][0]), to_tf32(acc[i][4]),
                      to_tf32(acc[i][1]), to_tf32(acc[i][5]) };
        float4 f1 = { to_tf32(acc[i][2]), to_tf32(acc[i][6]),
                      to_tf32(acc[i][3]), to_tf32(acc[i][7]) };
        *(float4*)&g_tmpf[base]     = f0;
        *(float4*)&g_tmpf[base + 4] = f1;
    }
}

// ---------------------------------------------------------------------------
// Pack W2 into GEMM2-B fragment-major (tf32).
// ---------------------------------------------------------------------------
__global__ __launch_bounds__(256) void pack_w2_kernel(const float* __restrict__ W2)
{
    const int gid = blockIdx.x * 256 + threadIdx.x;   // 65536
    const int lane = gid & 31;
    const int ks   = (gid >> 5) & 3;
    const int kt   = (gid >> 7) & 31;
    const int chk  = gid >> 12;
    const int g = lane >> 2, t = lane & 3;
    const int h = chk * 32 + ks * 8 + t;
    const int k = kt * 8 + g;
    g_w2f[gid * 2 + 0] = to_tf32(W2[h * 256 + k]);
    g_w2f[gid * 2 + 1] = to_tf32(W2[(h + 4) * 256 + k]);
}

// ---------------------------------------------------------------------------
// Pack z into GEMM1-A fragment-major (tf32).
// ---------------------------------------------------------------------------
__global__ __launch_bounds__(256) void pack_z_kernel(const float* __restrict__ z)
{
    const int gid = blockIdx.x * 256 + threadIdx.x;   // 8192
    const int lane = gid & 31;
    const int ks   = (gid >> 5) & 3;
    const int tile = gid >> 7;
    const int g = lane >> 2, t = lane & 3;
    const int r0 = tile * 16 + g;
    const int c0 = ks * 8 + t;
    g_zf[gid * 4 + 0] = to_tf32(z[r0 * 32 + c0]);
    g_zf[gid * 4 + 1] = to_tf32(z[(r0 + 8) * 32 + c0]);
    g_zf[gid * 4 + 2] = to_tf32(z[r0 * 32 + c0 + 4]);
    g_zf[gid * 4 + 3] = to_tf32(z[(r0 + 8) * 32 + c0 + 4]);
}

// ---------------------------------------------------------------------------
// Main fused kernel: grid 4096 = (b, i, jt of 4), 256 threads, 2 CTAs/SM.
// Warp w: j-tile rt = w&3 (16 rows), k-half kh = w>>2 (128 of 256 k).
// GEMM1 per warp over full 32-h chunk; C->A via shuffles; GEMM2 from regs.
// One __syncthreads per chunk.
// ---------------------------------------------------------------------------
#define SM_Z    0
#define SM_TMP  2048
#define SM_W2   4096
#define SM_B1   20480
#define SM_B2   20992
#define SM_W3   21248
#define SM_RED  21504
#define SM_TOT  21632          // floats = 86528 bytes

__global__ __launch_bounds__(256, 2) void decoder_main_kernel(
    const float* __restrict__ motif,
    const float* __restrict__ b1, const float* __restrict__ b2,
    const float* __restrict__ W3, const float* __restrict__ b3,
    float* __restrict__ out)
{
    extern __shared__ float sm[];
    const uint32_t s_u32 = (uint32_t)__cvta_generic_to_shared(sm);

    const int cta = blockIdx.x;
    const int jt  = cta & 3;
    const int i   = (cta >> 2) & 255;
    const int b   = cta >> 10;
    const int bi  = b * 256 + i;
    const int j0  = jt * 64;

    const int tid  = threadIdx.x;
    const int w    = tid >> 5;
    const int lane = tid & 31;
    const int g    = lane >> 2;
    const int t    = lane & 3;

    const int rt = w & 3;          // j-tile (16 rows)
    const int kh = w >> 2;         // k-half (128 cols)

    // shuffle source lanes for C->A conversion
    const int srcA = g * 4 + (t >> 1);
    const int srcB = srcA + 2;
    const bool odd = (t & 1);

    // ---- prologue: async loads of zjs + chunk 0 -------------------------
    {
        const float4* zsrc = (const float4*)(g_zf + ((size_t)((b * 256 + j0) >> 4)) * 512);
        cp16(s_u32 + (SM_Z + tid * 4) * 4, zsrc + tid);
        cp16(s_u32 + (SM_Z + (tid + 256) * 4) * 4, zsrc + tid + 256);
        const float4* wsrc = (const float4*)(g_w2f);
#pragma unroll
        for (int r = 0; r < 8; r++)
            cp16(s_u32 + (SM_W2 + (tid + r * 256) * 4) * 4, wsrc + tid + r * 256);
        const float4* tsrc = (const float4*)(g_tmpf + (size_t)bi * CH);
        cp16(s_u32 + (SM_TMP + tid * 4) * 4, tsrc + tid);
        cp_commit();
    }
    for (int idx = tid; idx < 1024; idx += 256) {
        if (idx < 512)       sm[SM_B1 + idx] = b1[idx];
        else if (idx < 768)  sm[SM_B2 + idx - 512] = b2[idx - 512];
        else                 sm[SM_W3 + idx - 768] = W3[idx - 768];
    }

    float acc2[16][4];
#pragma unroll
    for (int nt = 0; nt < 16; nt++)
#pragma unroll
        for (int r = 0; r < 4; r++) acc2[nt][r] = 0.f;

    int buf = 0;
    for (int chk = 0; chk < 16; chk++) {
        cp_wait0();
        __syncthreads();

        // prefetch next chunk into other buffer (overlaps compute)
        if (chk < 15) {
            const int nb = buf ^ 1;
            const float4* wsrc = (const float4*)(g_w2f + (chk + 1) * 8192);
#pragma unroll
            for (int r = 0; r < 8; r++)
                cp16(s_u32 + (SM_W2 + nb * 8192 + (tid + r * 256) * 4) * 4,
                     wsrc + tid + r * 256);
            const float4* tsrc = (const float4*)(g_tmpf + (size_t)bi * CH + (chk + 1) * 1024);
            cp16(s_u32 + (SM_TMP + nb * 1024 + tid * 4) * 4, tsrc + tid);
            cp_commit();
        }

        const float* tb = sm + SM_TMP + buf * 1024;
        const float* wb = sm + SM_W2 + buf * 8192;

        // ---- GEMM1: acc1 = z_jtile . tmp^T  (16j x 32h, full chunk) -----
        float acc1[4][4];
#pragma unroll
        for (int nt = 0; nt < 4; nt++)
#pragma unroll
            for (int r = 0; r < 4; r++) acc1[nt][r] = 0.f;

#pragma unroll
        for (int ks = 0; ks < 4; ks++) {
            float4 av = *(const float4*)&sm[SM_Z + ((rt * 4 + ks) * 32 + lane) * 4];
            uint32_t a[4] = { __float_as_uint(av.x), __float_as_uint(av.y),
                              __float_as_uint(av.z), __float_as_uint(av.w) };
#pragma unroll
            for (int nt = 0; nt < 4; nt++) {
                float2 bv = *(const float2*)&tb[((nt * 4 + ks) * 32 + lane) * 2];
                MMA_TF32(acc1[nt], a, __float_as_uint(bv.x), __float_as_uint(bv.y));
            }
        }
        // bias + relu + tf32 round, in place
#pragma unroll
        for (int nt = 0; nt < 4; nt++)
#pragma unroll
            for (int r = 0; r < 4; r++) {
                int col = nt * 8 + t * 2 + (r & 1);
                float v = fmaxf(acc1[nt][r] + sm[SM_B1 + chk * 32 + col], 0.f);
                acc1[nt][r] = to_tf32(v);
            }

        // ---- GEMM2: acc2 += h1 . W2chunk, A-frags built via shuffles ----
#pragma unroll
        for (int ks = 0; ks < 4; ks++) {
            float v0a = __shfl_sync(0xffffffffu, acc1[ks][0], srcA);
            float v1a = __shfl_sync(0xffffffffu, acc1[ks][1], srcA);
            float v2a = __shfl_sync(0xffffffffu, acc1[ks][2], srcA);
            float v3a = __shfl_sync(0xffffffffu, acc1[ks][3], srcA);
            float v0b = __shfl_sync(0xffffffffu, acc1[ks][0], srcB);
            float v1b = __shfl_sync(0xffffffffu, acc1[ks][1], srcB);
            float v2b = __shfl_sync(0xffffffffu, acc1[ks][2], srcB);
            float v3b = __shfl_sync(0xffffffffu, acc1[ks][3], srcB);
            uint32_t a[4];
            a[0] = __float_as_uint(odd ? v1a : v0a);
            a[1] = __float_as_uint(odd ? v3a : v2a);
            a[2] = __float_as_uint(odd ? v1b : v0b);
            a[3] = __float_as_uint(odd ? v3b : v2b);
#pragma unroll
            for (int nt = 0; nt < 16; nt++) {
                const int kt = kh * 16 + nt;
                float2 bv = *(const float2*)&wb[((kt * 4 + ks) * 32 + lane) * 2];
                MMA_TF32(acc2[nt], a, __float_as_uint(bv.x), __float_as_uint(bv.y));
            }
        }
        buf ^= 1;
    }

    // ---- epilogue: relu(+b2) . W3, reduce, mask, sigmoid -----------------
    float psum[2] = {0.f, 0.f};
#pragma unroll
    for (int nt = 0; nt < 16; nt++)
#pragma unroll
        for (int r = 0; r < 4; r++) {
            int k = (kh * 16 + nt) * 8 + t * 2 + (r & 1);
            float h2 = fmaxf(acc2[nt][r] + sm[SM_B2 + k], 0.f);
            psum[r >> 1] += h2 * sm[SM_W3 + k];
        }
#pragma unroll
    for (int u = 0; u < 2; u++) {
        float v = psum[u];
        v += __shfl_xor_sync(0xffffffffu, v, 1);
        v += __shfl_xor_sync(0xffffffffu, v, 2);
        psum[u] = v;
    }
    __syncthreads();
    if (t == 0) {
#pragma unroll
        for (int u = 0; u < 2; u++) {
            int row = rt * 16 + g + u * 8;
            sm[SM_RED + row * 2 + kh] = psum[u];
        }
    }
    __syncthreads();

    if (tid < 64) {
        float logit = sm[SM_RED + tid * 2] + sm[SM_RED + tid * 2 + 1] + b3[0];
        float mask  = motif[b * 256 + i] * motif[b * 256 + j0 + tid];
        logit *= mask;
        float cmap = 1.f / (1.f + __expf(-logit));
        size_t base = ((size_t)b * 256 + i) * 256 + j0 + tid;
        out[base]       = cmap;
        out[BNN + base] = logit;
    }
}

// ---------------------------------------------------------------------------
extern "C" void kernel_launch(void* const* d_in, const int* in_sizes, int n_in,
                              void* d_out, int out_size)
{
    const float* z     = (const float*)d_in[0];
    const float* motif = (const float*)d_in[1];
    const float* W1    = (const float*)d_in[3];
    const float* b1    = (const float*)d_in[4];
    const float* W2    = (const float*)d_in[5];
    const float* b2    = (const float*)d_in[6];
    const float* W3    = (const float*)d_in[7];
    const float* b3    = (const float*)d_in[8];
    float* out = (float*)d_out;

    (void)in_sizes; (void)n_in; (void)out_size;

    cudaFuncSetAttribute(decoder_main_kernel,
                         cudaFuncAttributeMaxDynamicSharedMemorySize,
                         SM_TOT * (int)sizeof(float));

    stage_a_kernel<<<dim3(128, 16), 256>>>(z, W1);
    pack_w2_kernel<<<256, 256>>>(W2);
    pack_z_kernel<<<32, 256>>>(z);
    decoder_main_kernel<<<4096, 256, SM_TOT * sizeof(float)>>>(
        motif, b1, b2, W3, b3, out);
}

// round 10
// speedup vs baseline: 1.7110x; 1.0003x over previous
#include <cuda_runtime.h>
#include <cuda_bf16.h>
#include <cstdint>

// ---------------------------------------------------------------------------
// Decoder_84731114815924  (B=4, N=256, D=32, H=512)
// mma.sync tf32. R10: 128-thr CTAs, M64xN64 GEMM2 warp tiles (fragment
// replication cut), z A-frags register-resident, h1 via small frag-major smem.
// ---------------------------------------------------------------------------

#define BN    1024
#define CH    16384
#define BNN   262144

__device__ float g_tmpf[BN * CH];        // 64 MB: GEMM1-B fragment-major tmp
__device__ float g_w2f[16 * 32 * 4 * 64];// 512 KB: GEMM2-B fragment-major W2
__device__ float g_zf[64 * 4 * 32 * 4];  // 128 KB: GEMM1-A fragment-major z

__device__ __forceinline__ float to_tf32(float x) {
    uint32_t u;
    asm("cvt.rna.tf32.f32 %0, %1;" : "=r"(u) : "f"(x));
    return __uint_as_float(u);
}

#define MMA_TF32(D, A, B0, B1)                                              \
    asm volatile(                                                           \
        "mma.sync.aligned.m16n8k8.row.col.f32.tf32.tf32.f32 "               \
        "{%0,%1,%2,%3}, {%4,%5,%6,%7}, {%8,%9}, {%0,%1,%2,%3};\n"           \
        : "+f"(D[0]), "+f"(D[1]), "+f"(D[2]), "+f"(D[3])                    \
        : "r"(A[0]), "r"(A[1]), "r"(A[2]), "r"(A[3]), "r"(B0), "r"(B1))

__device__ __forceinline__ void cp16(uint32_t s, const void* g) {
    asm volatile("cp.async.cg.shared.global [%0], [%1], 16;" :: "r"(s), "l"(g));
}
__device__ __forceinline__ void cp_commit() {
    asm volatile("cp.async.commit_group;");
}
__device__ __forceinline__ void cp_wait0() {
    asm volatile("cp.async.wait_group 0;");
}

// ---------------------------------------------------------------------------
// Stage A: tmp[bi][c][h] = sum_a z[bi][a] * W1[a*16384 + c*512 + h], written
// into GEMM1-B fragment-major layout with float4 stores:
//   g_tmpf[((bi*16+chk)*16 + ntt*4 + ks)*64 + g*8 + t*2 + e]
//     = tmp[bi][c = ks*8 + t + 4e][h = chk*32 + ntt*8 + g]
// ---------------------------------------------------------------------------
__global__ __launch_bounds__(256) void stage_a_kernel(
    const float* __restrict__ z, const float* __restrict__ W1)
{
    __shared__ float zt[64][33];
    __shared__ float wt[32][132];
    const int oct = blockIdx.x & 3;
    const int hg  = blockIdx.x >> 2;
    const int bi0 = blockIdx.y * 64;
    const int c0  = oct * 8, h0 = hg * 16;
    const int tid = threadIdx.x;

    for (int idx = tid; idx < 64 * 32; idx += 256) {
        int r = idx >> 5, a = idx & 31;
        zt[r][a] = z[(bi0 + r) * 32 + a];
    }
    for (int idx = tid; idx < 32 * 128; idx += 256) {
        int a = idx >> 7, col = idx & 127;
        int ci = col >> 4, hi = col & 15;
        wt[a][col] = W1[a * CH + (c0 + ci) * 512 + h0 + hi];
    }
    __syncthreads();

    const int tm = tid >> 4;
    const int tn = tid & 15;

    float acc[4][8];
#pragma unroll
    for (int i = 0; i < 4; i++)
#pragma unroll
        for (int j = 0; j < 8; j++) acc[i][j] = 0.f;

#pragma unroll
    for (int k = 0; k < 32; k++) {
        float a[4], bb[8];
#pragma unroll
        for (int i = 0; i < 4; i++) a[i] = zt[tm * 4 + i][k];
#pragma unroll
        for (int j = 0; j < 8; j++) bb[j] = wt[k][j * 16 + tn];
#pragma unroll
        for (int i = 0; i < 4; i++)
#pragma unroll
            for (int j = 0; j < 8; j++) acc[i][j] = fmaf(a[i], bb[j], acc[i][j]);
    }

    const int h   = h0 + tn;
    const int chk = h >> 5;
    const int ntt = (h >> 3) & 3;
    const int g   = h & 7;
#pragma unroll
    for (int i = 0; i < 4; i++) {
        const int bi = bi0 + tm * 4 + i;
        const size_t base = (((size_t)bi * 16 + chk) * 16 + ntt * 4 + oct) * 64 + g * 8;
        float4 f0 = { to_tf32(acc[i][0]), to_tf32(acc[i][4]),
                      to_tf32(acc[i][1]), to_tf32(acc[i][5]) };
        float4 f1 = { to_tf32(acc[i][2]), to_tf32(acc[i][6]),
                      to_tf32(acc[i][3]), to_tf32(acc[i][7]) };
        *(float4*)&g_tmpf[base]     = f0;
        *(float4*)&g_tmpf[base + 4] = f1;
    }
}

// ---------------------------------------------------------------------------
// Pack W2 into GEMM2-B fragment-major (tf32).
// ---------------------------------------------------------------------------
__global__ __launch_bounds__(256) void pack_w2_kernel(const float* __restrict__ W2)
{
    const int gid = blockIdx.x * 256 + threadIdx.x;   // 65536
    const int lane = gid & 31;
    const int ks   = (gid >> 5) & 3;
    const int kt   = (gid >> 7) & 31;
    const int chk  = gid >> 12;
    const int g = lane >> 2, t = lane & 3;
    const int h = chk * 32 + ks * 8 + t;
    const int k = kt * 8 + g;
    g_w2f[gid * 2 + 0] = to_tf32(W2[h * 256 + k]);
    g_w2f[gid * 2 + 1] = to_tf32(W2[(h + 4) * 256 + k]);
}

// ---------------------------------------------------------------------------
// Pack z into GEMM1-A fragment-major (tf32).
// ---------------------------------------------------------------------------
__global__ __launch_bounds__(256) void pack_z_kernel(const float* __restrict__ z)
{
    const int gid = blockIdx.x * 256 + threadIdx.x;   // 8192
    const int lane = gid & 31;
    const int ks   = (gid >> 5) & 3;
    const int tile = gid >> 7;
    const int g = lane >> 2, t = lane & 3;
    const int r0 = tile * 16 + g;
    const int c0 = ks * 8 + t;
    g_zf[gid * 4 + 0] = to_tf32(z[r0 * 32 + c0]);
    g_zf[gid * 4 + 1] = to_tf32(z[(r0 + 8) * 32 + c0]);
    g_zf[gid * 4 + 2] = to_tf32(z[r0 * 32 + c0 + 4]);
    g_zf[gid * 4 + 3] = to_tf32(z[(r0 + 8) * 32 + c0 + 4]);
}

// ---------------------------------------------------------------------------
// Main fused kernel: grid 4096 = (b, i, jt of 4), 128 threads, 2 CTAs/SM.
// Warp w (0..3):
//   GEMM1: owns j-rows [w*16, w*16+16), full 32-h chunk (16 MMAs, no dup).
//   GEMM2: all 64 j-rows x k-quarter [w*64, w*64+64) (4mt x 8nt x 4ks).
// h1 passes through frag-major smem: [mt][ks][qp][33 lanes x 2] stride 66.
// z A-frags register-resident (chunk-invariant).
// ---------------------------------------------------------------------------
#define SM_TMP  0
#define SM_W2   2048
#define SM_H1   18432
#define SM_B1   20544
#define SM_B2   21056
#define SM_W3   21312
#define SM_RED  21568
#define SM_TOT  21824          // floats = 87296 bytes

__global__ __launch_bounds__(128, 2) void decoder_main_kernel(
    const float* __restrict__ motif,
    const float* __restrict__ b1, const float* __restrict__ b2,
    const float* __restrict__ W3, const float* __restrict__ b3,
    float* __restrict__ out)
{
    extern __shared__ float sm[];
    const uint32_t s_u32 = (uint32_t)__cvta_generic_to_shared(sm);

    const int cta = blockIdx.x;
    const int jt  = cta & 3;
    const int i   = (cta >> 2) & 255;
    const int b   = cta >> 10;
    const int bi  = b * 256 + i;
    const int j0  = jt * 64;

    const int tid  = threadIdx.x;
    const int w    = tid >> 5;
    const int lane = tid & 31;
    const int g    = lane >> 2;
    const int t    = lane & 3;

    // ---- z A-frags, register-resident for warp's 16 rows ----------------
    uint32_t za[4][4];
    {
        const int tile = ((b * 256 + j0) >> 4) + w;
        const float4* zf4 = (const float4*)g_zf;
#pragma unroll
        for (int ks = 0; ks < 4; ks++) {
            float4 v = zf4[(tile * 4 + ks) * 32 + lane];
            za[ks][0] = __float_as_uint(v.x); za[ks][1] = __float_as_uint(v.y);
            za[ks][2] = __float_as_uint(v.z); za[ks][3] = __float_as_uint(v.w);
        }
    }

    // ---- prologue: async loads of chunk 0 -------------------------------
    {
        const float4* wsrc = (const float4*)(g_w2f);
#pragma unroll
        for (int r = 0; r < 16; r++)
            cp16(s_u32 + (SM_W2 + (tid + r * 128) * 4) * 4, wsrc + tid + r * 128);
        const float4* tsrc = (const float4*)(g_tmpf + (size_t)bi * CH);
        cp16(s_u32 + (SM_TMP + tid * 4) * 4, tsrc + tid);
        cp16(s_u32 + (SM_TMP + (tid + 128) * 4) * 4, tsrc + tid + 128);
        cp_commit();
    }
    for (int idx = tid; idx < 1024; idx += 128) {
        if (idx < 512)       sm[SM_B1 + idx] = b1[idx];
        else if (idx < 768)  sm[SM_B2 + idx - 512] = b2[idx - 512];
        else                 sm[SM_W3 + idx - 768] = W3[idx - 768];
    }

    float acc2[4][8][4];
#pragma unroll
    for (int mt = 0; mt < 4; mt++)
#pragma unroll
        for (int nt = 0; nt < 8; nt++)
#pragma unroll
            for (int r = 0; r < 4; r++) acc2[mt][nt][r] = 0.f;

    int buf = 0;
    for (int chk = 0; chk < 16; chk++) {
        cp_wait0();
        __syncthreads();

        // prefetch next chunk into other buffer
        if (chk < 15) {
            const int nb = buf ^ 1;
            const float4* wsrc = (const float4*)(g_w2f + (chk + 1) * 8192);
#pragma unroll
            for (int r = 0; r < 16; r++)
                cp16(s_u32 + (SM_W2 + nb * 8192 + (tid + r * 128) * 4) * 4,
                     wsrc + tid + r * 128);
            const float4* tsrc = (const float4*)(g_tmpf + (size_t)bi * CH + (chk + 1) * 1024);
            cp16(s_u32 + (SM_TMP + nb * 1024 + tid * 4) * 4, tsrc + tid);
            cp16(s_u32 + (SM_TMP + nb * 1024 + (tid + 128) * 4) * 4, tsrc + tid + 128);
            cp_commit();
        }

        const float* tb = sm + SM_TMP + buf * 1024;
        const float* wb = sm + SM_W2 + buf * 8192;

        // ---- GEMM1: acc1 = z_rows(w) . tmp^T  (16j x 32h) ---------------
        float acc1[4][4];
#pragma unroll
        for (int nt = 0; nt < 4; nt++)
#pragma unroll
            for (int r = 0; r < 4; r++) acc1[nt][r] = 0.f;

#pragma unroll
        for (int ks = 0; ks < 4; ks++)
#pragma unroll
            for (int nt = 0; nt < 4; nt++) {
                float2 bv = *(const float2*)&tb[((nt * 4 + ks) * 32 + lane) * 2];
                MMA_TF32(acc1[nt], za[ks], __float_as_uint(bv.x), __float_as_uint(bv.y));
            }

        // bias+relu+round, store frag-major h1: [mt][ks2][qp][lane*2+e] stride 66
#pragma unroll
        for (int nt = 0; nt < 4; nt++)
#pragma unroll
            for (int r = 0; r < 4; r++) {
                int col = nt * 8 + t * 2 + (r & 1);
                float v = fmaxf(acc1[nt][r] + sm[SM_B1 + chk * 32 + col], 0.f);
                int c  = t * 2 + (r & 1);        // col within octet
                int qp = c >> 2;
                int lt = g * 4 + (c & 3);
                sm[SM_H1 + ((w * 4 + nt) * 2 + qp) * 66 + lt * 2 + (r >> 1)] = to_tf32(v);
            }
        __syncthreads();

        // ---- GEMM2: acc2 += h1(all 64j) . W2(k-quarter w) ---------------
#pragma unroll
        for (int ks = 0; ks < 4; ks++) {
            uint32_t B[8][2];
#pragma unroll
            for (int nt = 0; nt < 8; nt++) {
                float2 bv = *(const float2*)&wb[(((w * 8 + nt) * 4 + ks) * 32 + lane) * 2];
                B[nt][0] = __float_as_uint(bv.x);
                B[nt][1] = __float_as_uint(bv.y);
            }
#pragma unroll
            for (int mt = 0; mt < 4; mt++) {
                uint32_t A[4];
                float2 a0 = *(const float2*)&sm[SM_H1 + ((mt * 4 + ks) * 2 + 0) * 66 + lane * 2];
                float2 a1 = *(const float2*)&sm[SM_H1 + ((mt * 4 + ks) * 2 + 1) * 66 + lane * 2];
                A[0] = __float_as_uint(a0.x); A[1] = __float_as_uint(a0.y);
                A[2] = __float_as_uint(a1.x); A[3] = __float_as_uint(a1.y);
#pragma unroll
                for (int nt = 0; nt < 8; nt++)
                    MMA_TF32(acc2[mt][nt], A, B[nt][0], B[nt][1]);
            }
        }
        buf ^= 1;
    }

    // ---- epilogue: relu(+b2) . W3 over k-quarter, reduce, mask, sigmoid --
#pragma unroll
    for (int mt = 0; mt < 4; mt++) {
        float ps[2] = {0.f, 0.f};
#pragma unroll
        for (int nt = 0; nt < 8; nt++)
#pragma unroll
            for (int r = 0; r < 4; r++) {
                int k = w * 64 + nt * 8 + t * 2 + (r & 1);
                float h2 = fmaxf(acc2[mt][nt][r] + sm[SM_B2 + k], 0.f);
                ps[r >> 1] += h2 * sm[SM_W3 + k];
            }
#pragma unroll
        for (int u = 0; u < 2; u++) {
            float v = ps[u];
            v += __shfl_xor_sync(0xffffffffu, v, 1);
            v += __shfl_xor_sync(0xffffffffu, v, 2);
            ps[u] = v;
        }
        if (t == 0) {
            sm[SM_RED + (mt * 16 + g) * 4 + w]     = ps[0];
            sm[SM_RED + (mt * 16 + g + 8) * 4 + w] = ps[1];
        }
    }
    __syncthreads();

    if (tid < 64) {
        const float* red = sm + SM_RED + tid * 4;
        float logit = red[0] + red[1] + red[2] + red[3] + b3[0];
        float mask  = motif[b * 256 + i] * motif[b * 256 + j0 + tid];
        logit *= mask;
        float cmap = 1.f / (1.f + __expf(-logit));
        size_t base = ((size_t)b * 256 + i) * 256 + j0 + tid;
        out[base]       = cmap;
        out[BNN + base] = logit;
    }
}

// ---------------------------------------------------------------------------
extern "C" void kernel_launch(void* const* d_in, const int* in_sizes, int n_in,
                              void* d_out, int out_size)
{
    const float* z     = (const float*)d_in[0];
    const float* motif = (const float*)d_in[1];
    const float* W1    = (const float*)d_in[3];
    const float* b1    = (const float*)d_in[4];
    const float* W2    = (const float*)d_in[5];
    const float* b2    = (const float*)d_in[6];
    const float* W3    = (const float*)d_in[7];
    const float* b3    = (const float*)d_in[8];
    float* out = (float*)d_out;

    (void)in_sizes; (void)n_in; (void)out_size;

    cudaFuncSetAttribute(decoder_main_kernel,
                         cudaFuncAttributeMaxDynamicSharedMemorySize,
                         SM_TOT * (int)sizeof(float));

    stage_a_kernel<<<dim3(128, 16), 256>>>(z, W1);
    pack_w2_kernel<<<256, 256>>>(W2);
    pack_z_kernel<<<32, 256>>>(z);
    decoder_main_kernel<<<4096, 128, SM_TOT * sizeof(float)>>>(
        motif, b1, b2, W3, b3, out);
}

// round 11
// speedup vs baseline: 3.4962x; 2.0434x over previous
#include <cuda_runtime.h>
#include <cuda_fp16.h>
#include <cstdint>

// ---------------------------------------------------------------------------
// Decoder_84731114815924  (B=4, N=256, D=32, H=512)
// R11: fp16 mma.sync m16n8k16 (fp32 accum). Halves MMA count & operand bytes
// vs tf32. GEMM1 C-frag == GEMM2 A-frag in registers (no h1 smem/shuffles).
// ---------------------------------------------------------------------------

#define BNN   262144

__device__ uint32_t g_tmph[1024 * 16 * 512]; // 32 MB: per (bi,chk) B-frags (fp16)
__device__ uint32_t g_w2h[16 * 4096];        // 256 KB: per-chk GEMM2 B-frags
__device__ uint32_t g_zh[16384];             // 64 KB: GEMM1 A-frags

__device__ __forceinline__ uint32_t ph2(float a, float b) {
    __half2 h = __floats2half2_rn(a, b);
    return *(uint32_t*)&h;
}

#define MMA_F16(D, A, B0, B1)                                               \
    asm volatile(                                                           \
        "mma.sync.aligned.m16n8k16.row.col.f32.f16.f16.f32 "                \
        "{%0,%1,%2,%3}, {%4,%5,%6,%7}, {%8,%9}, {%0,%1,%2,%3};\n"           \
        : "+f"(D[0]), "+f"(D[1]), "+f"(D[2]), "+f"(D[3])                    \
        : "r"(A[0]), "r"(A[1]), "r"(A[2]), "r"(A[3]), "r"(B0), "r"(B1))

__device__ __forceinline__ void cp16(uint32_t s, const void* g) {
    asm volatile("cp.async.cg.shared.global [%0], [%1], 16;" :: "r"(s), "l"(g));
}
__device__ __forceinline__ void cp_commit() { asm volatile("cp.async.commit_group;"); }
__device__ __forceinline__ void cp_wait0()  { asm volatile("cp.async.wait_group 0;"); }

// ---------------------------------------------------------------------------
// Stage A: tmp[bi][c][h] = sum_a z[bi][a] * W1[a*16384 + c*512 + h], emitted
// as fp16 GEMM1 B-fragments:
//   u32 idx = (bi*16+chk)*512 + ((ntile*2+s)*2+bh)*32 + lane,
//   val = {tmp[c][h], tmp[c+1][h]},  h = chk*32+ntile*8+(lane>>2),
//                                    c = s*16+bh*8+(lane&3)*2.
// Thread owns one h, 8 consecutive c (oct*8..+7) -> one uint4 store per bi.
// ---------------------------------------------------------------------------
__global__ __launch_bounds__(256) void stage_a_kernel(
    const float* __restrict__ z, const float* __restrict__ W1)
{
    __shared__ float zt[64][33];
    __shared__ float wt[32][132];
    const int oct = blockIdx.x & 3;        // c-octet: s = oct>>1, bh = oct&1
    const int hg  = blockIdx.x >> 2;       // h0 = hg*16
    const int bi0 = blockIdx.y * 64;
    const int c0  = oct * 8, h0 = hg * 16;
    const int tid = threadIdx.x;

    for (int idx = tid; idx < 64 * 32; idx += 256) {
        int r = idx >> 5, a = idx & 31;
        zt[r][a] = z[(bi0 + r) * 32 + a];
    }
    for (int idx = tid; idx < 32 * 128; idx += 256) {
        int a = idx >> 7, col = idx & 127;
        int ci = col >> 4, hi = col & 15;
        wt[a][col] = W1[a * 16384 + (c0 + ci) * 512 + h0 + hi];
    }
    __syncthreads();

    const int tm = tid >> 4;
    const int tn = tid & 15;

    float acc[4][8];
#pragma unroll
    for (int i = 0; i < 4; i++)
#pragma unroll
        for (int j = 0; j < 8; j++) acc[i][j] = 0.f;

#pragma unroll
    for (int k = 0; k < 32; k++) {
        float a[4], bb[8];
#pragma unroll
        for (int i = 0; i < 4; i++) a[i] = zt[tm * 4 + i][k];
#pragma unroll
        for (int j = 0; j < 8; j++) bb[j] = wt[k][j * 16 + tn];
#pragma unroll
        for (int i = 0; i < 4; i++)
#pragma unroll
            for (int j = 0; j < 8; j++) acc[i][j] = fmaf(a[i], bb[j], acc[i][j]);
    }

    const int h   = h0 + tn;
    const int chk = h >> 5;
    const int nt  = (h >> 3) & 3;
    const int g   = h & 7;
    const int s   = oct >> 1, bh = oct & 1;
#pragma unroll
    for (int i = 0; i < 4; i++) {
        const int bi = bi0 + tm * 4 + i;
        uint4 v;
        v.x = ph2(acc[i][0], acc[i][1]);
        v.y = ph2(acc[i][2], acc[i][3]);
        v.z = ph2(acc[i][4], acc[i][5]);
        v.w = ph2(acc[i][6], acc[i][7]);
        ((uint4*)g_tmph)[(size_t)(bi * 16 + chk) * 128 + ((nt * 2 + s) * 2 + bh) * 8 + g] = v;
    }
}

// ---------------------------------------------------------------------------
// Pack W2 -> fp16 GEMM2 B-frags: u32 idx = chk*4096 + (nt*2+s)*64 + lane*2 + bh
//   val = {W2[h][k2], W2[h+1][k2]}, h = chk*32+s*16+bh*8+(lane&3)*2, k2 = nt*8+(lane>>2)
// ---------------------------------------------------------------------------
__global__ __launch_bounds__(256) void pack_w2_kernel(const float* __restrict__ W2)
{
    const int gid  = blockIdx.x * 256 + threadIdx.x;   // 65536
    const int bh   = gid & 1;
    const int lane = (gid >> 1) & 31;
    const int s    = (gid >> 6) & 1;
    const int nt   = (gid >> 7) & 31;
    const int chk  = gid >> 12;
    const int h  = chk * 32 + s * 16 + bh * 8 + (lane & 3) * 2;
    const int k2 = nt * 8 + (lane >> 2);
    g_w2h[gid] = ph2(W2[h * 256 + k2], W2[(h + 1) * 256 + k2]);
}

// ---------------------------------------------------------------------------
// Pack z -> fp16 GEMM1 A-frags: u32 idx = (tile*2+s)*128 + lane*4 + r
//   r0={z[g][s16+t2],+1} r1={row+8} r2={col+8} r3={row+8,col+8}
// ---------------------------------------------------------------------------
__global__ __launch_bounds__(256) void pack_z_kernel(const float* __restrict__ z)
{
    const int gid  = blockIdx.x * 256 + threadIdx.x;   // 16384
    const int r    = gid & 3;
    const int lane = (gid >> 2) & 31;
    const int s    = (gid >> 7) & 1;
    const int tile = gid >> 8;
    const int g = lane >> 2, t = lane & 3;
    const int row = tile * 16 + g + (r & 1) * 8;
    const int col = s * 16 + t * 2 + (r >> 1) * 8;
    g_zh[gid] = ph2(z[row * 32 + col], z[row * 32 + col + 1]);
}

// ---------------------------------------------------------------------------
// Main fused kernel: grid 4096 = (b, i, jt of 4), 128 threads, 2 CTAs/SM.
// Warp w owns j rows [w*16, w*16+16) end-to-end:
//   GEMM1: 16j x 32h chunk (8 MMAs), C-frag -> relu+bias -> fp16 A-frag in regs
//   GEMM2: 16j x 256k2 (2 ks x 32 nt = 64 MMAs), acc2[32][4] fp32.
// No intra-chunk cross-warp dependency; 1 barrier/chunk for double buffer.
// smem u32 region: tmp 2x512 @0, w2 2x4096 @1024; floats: b1@9216 b2@9728 w3@9984.
// ---------------------------------------------------------------------------
#define SM_TOT  10240          // floats = 40960 bytes

__global__ __launch_bounds__(128, 2) void decoder_main_kernel(
    const float* __restrict__ motif,
    const float* __restrict__ b1, const float* __restrict__ b2,
    const float* __restrict__ W3, const float* __restrict__ b3,
    float* __restrict__ out)
{
    extern __shared__ float sm[];
    uint32_t* smu = (uint32_t*)sm;
    const uint32_t s_u32 = (uint32_t)__cvta_generic_to_shared(sm);
    float* s_b1 = sm + 9216;
    float* s_b2 = sm + 9728;
    float* s_w3 = sm + 9984;

    const int cta = blockIdx.x;
    const int jt  = cta & 3;
    const int i   = (cta >> 2) & 255;
    const int b   = cta >> 10;
    const int bi  = b * 256 + i;
    const int j0  = jt * 64;

    const int tid  = threadIdx.x;
    const int w    = tid >> 5;
    const int lane = tid & 31;
    const int g    = lane >> 2;
    const int t    = lane & 3;

    // ---- z A-frags, register-resident (chunk-invariant) ------------------
    uint32_t za[2][4];
    {
        const int tile = ((b * 256 + j0) >> 4) + w;
        const uint4* zf = (const uint4*)g_zh;
#pragma unroll
        for (int s = 0; s < 2; s++) {
            uint4 v = zf[(tile * 2 + s) * 32 + lane];
            za[s][0] = v.x; za[s][1] = v.y; za[s][2] = v.z; za[s][3] = v.w;
        }
    }

    // ---- prologue: async loads of chunk 0 --------------------------------
    {
        const uint4* wsrc = (const uint4*)g_w2h;
#pragma unroll
        for (int r = 0; r < 8; r++)
            cp16(s_u32 + (1024 + (tid + r * 128) * 4) * 4, wsrc + tid + r * 128);
        const uint4* tsrc = (const uint4*)g_tmph + (size_t)bi * 16 * 128;
        cp16(s_u32 + (tid * 4) * 4, tsrc + tid);
        cp_commit();
    }
    for (int idx = tid; idx < 1024; idx += 128) {
        if (idx < 512)       s_b1[idx] = b1[idx];
        else if (idx < 768)  s_b2[idx - 512] = b2[idx - 512];
        else                 s_w3[idx - 768] = W3[idx - 768];
    }

    float acc2[32][4];
#pragma unroll
    for (int nt = 0; nt < 32; nt++)
#pragma unroll
        for (int r = 0; r < 4; r++) acc2[nt][r] = 0.f;

    int buf = 0;
    for (int chk = 0; chk < 16; chk++) {
        cp_wait0();
        __syncthreads();

        if (chk < 15) {
            const int nb = buf ^ 1;
            const uint4* wsrc = (const uint4*)g_w2h + (chk + 1) * 1024;
#pragma unroll
            for (int r = 0; r < 8; r++)
                cp16(s_u32 + (1024 + nb * 4096 + (tid + r * 128) * 4) * 4,
                     wsrc + tid + r * 128);
            const uint4* tsrc = (const uint4*)g_tmph + ((size_t)bi * 16 + chk + 1) * 128;
            cp16(s_u32 + (nb * 512 + tid * 4) * 4, tsrc + tid);
            cp_commit();
        }

        const uint32_t* tb = smu + buf * 512;
        const uint32_t* wb = smu + 1024 + buf * 4096;

        // ---- GEMM1: acc1 = z_rows(w) . tmp^T  (16j x 32h) ----------------
        float acc1[4][4];
#pragma unroll
        for (int nt = 0; nt < 4; nt++)
#pragma unroll
            for (int r = 0; r < 4; r++) acc1[nt][r] = 0.f;

#pragma unroll
        for (int s = 0; s < 2; s++)
#pragma unroll
            for (int nt = 0; nt < 4; nt++) {
                uint32_t b0 = tb[((nt * 2 + s) * 2 + 0) * 32 + lane];
                uint32_t bb = tb[((nt * 2 + s) * 2 + 1) * 32 + lane];
                MMA_F16(acc1[nt], za[s], b0, bb);
            }

        // bias + relu + fp16 pack: C-frag -> A-frag, all in registers
        uint32_t h1h[4][2];
#pragma unroll
        for (int nt = 0; nt < 4; nt++) {
            const float* bb = s_b1 + chk * 32 + nt * 8 + t * 2;
            float v0 = fmaxf(acc1[nt][0] + bb[0], 0.f);
            float v1 = fmaxf(acc1[nt][1] + bb[1], 0.f);
            float v2 = fmaxf(acc1[nt][2] + bb[0], 0.f);
            float v3 = fmaxf(acc1[nt][3] + bb[1], 0.f);
            h1h[nt][0] = ph2(v0, v1);
            h1h[nt][1] = ph2(v2, v3);
        }

        // ---- GEMM2: acc2 += h1(16j) . W2chunk (256 k2) -------------------
#pragma unroll
        for (int s = 0; s < 2; s++) {
            uint32_t A[4] = { h1h[2 * s][0], h1h[2 * s][1],
                              h1h[2 * s + 1][0], h1h[2 * s + 1][1] };
#pragma unroll
            for (int nt = 0; nt < 32; nt++) {
                uint2 bv = *(const uint2*)&wb[((nt * 2 + s) * 32 + lane) * 2];
                MMA_F16(acc2[nt], A, bv.x, bv.y);
            }
        }
        buf ^= 1;
    }

    // ---- epilogue: relu(+b2) . W3 (full k2 in-warp), quad-reduce ---------
    float ps0 = 0.f, ps1 = 0.f;
#pragma unroll
    for (int nt = 0; nt < 32; nt++) {
        const int k = nt * 8 + t * 2;
        float h2a = fmaxf(acc2[nt][0] + s_b2[k],     0.f);
        float h2b = fmaxf(acc2[nt][1] + s_b2[k + 1], 0.f);
        float h2c = fmaxf(acc2[nt][2] + s_b2[k],     0.f);
        float h2d = fmaxf(acc2[nt][3] + s_b2[k + 1], 0.f);
        ps0 = fmaf(h2a, s_w3[k], ps0);  ps0 = fmaf(h2b, s_w3[k + 1], ps0);
        ps1 = fmaf(h2c, s_w3[k], ps1);  ps1 = fmaf(h2d, s_w3[k + 1], ps1);
    }
    ps0 += __shfl_xor_sync(0xffffffffu, ps0, 1);
    ps0 += __shfl_xor_sync(0xffffffffu, ps0, 2);
    ps1 += __shfl_xor_sync(0xffffffffu, ps1, 1);
    ps1 += __shfl_xor_sync(0xffffffffu, ps1, 2);

    if (t == 0) {
        const float b3v = b3[0];
        const float mi  = motif[b * 256 + i];
#pragma unroll
        for (int u = 0; u < 2; u++) {
            const int j = j0 + w * 16 + g + u * 8;
            float logit = ((u ? ps1 : ps0) + b3v) * (mi * motif[b * 256 + j]);
            float cmap  = 1.f / (1.f + __expf(-logit));
            size_t base = (size_t)bi * 256 + j;
            out[base]       = cmap;
            out[BNN + base] = logit;
        }
    }
}

// ---------------------------------------------------------------------------
extern "C" void kernel_launch(void* const* d_in, const int* in_sizes, int n_in,
                              void* d_out, int out_size)
{
    const float* z     = (const float*)d_in[0];
    const float* motif = (const float*)d_in[1];
    const float* W1    = (const float*)d_in[3];
    const float* b1    = (const float*)d_in[4];
    const float* W2    = (const float*)d_in[5];
    const float* b2    = (const float*)d_in[6];
    const float* W3    = (const float*)d_in[7];
    const float* b3    = (const float*)d_in[8];
    float* out = (float*)d_out;

    (void)in_sizes; (void)n_in; (void)out_size;

    cudaFuncSetAttribute(decoder_main_kernel,
                         cudaFuncAttributeMaxDynamicSharedMemorySize,
                         SM_TOT * (int)sizeof(float));

    stage_a_kernel<<<dim3(128, 16), 256>>>(z, W1);
    pack_w2_kernel<<<256, 256>>>(W2);
    pack_z_kernel<<<64, 256>>>(z);
    decoder_main_kernel<<<4096, 128, SM_TOT * sizeof(float)>>>(
        motif, b1, b2, W3, b3, out);
}

// round 12
// speedup vs baseline: 3.7423x; 1.0704x over previous
#include <cuda_runtime.h>
#include <cuda_fp16.h>
#include <cstdint>

// ---------------------------------------------------------------------------
// Decoder_84731114815924  (B=4, N=256, D=32, H=512)
// R12: fp16 mma path + occupancy 3 CTAs/SM (170-reg cap) + uint4 W2 B-frags
// (one LDS.128 per nt-tile, loaded just-in-time -> lower reg pressure).
// ---------------------------------------------------------------------------

#define BNN   262144

__device__ uint32_t g_tmph[1024 * 16 * 512]; // 32 MB: per (bi,chk) GEMM1 B-frags
__device__ uint32_t g_w2h[16 * 4096];        // 256 KB: per-chk GEMM2 B-frags (uint4 tiles)
__device__ uint32_t g_zh[16384];             // 64 KB: GEMM1 A-frags

__device__ __forceinline__ uint32_t ph2(float a, float b) {
    __half2 h = __floats2half2_rn(a, b);
    return *(uint32_t*)&h;
}

#define MMA_F16(D, A, B0, B1)                                               \
    asm volatile(                                                           \
        "mma.sync.aligned.m16n8k16.row.col.f32.f16.f16.f32 "                \
        "{%0,%1,%2,%3}, {%4,%5,%6,%7}, {%8,%9}, {%0,%1,%2,%3};\n"           \
        : "+f"(D[0]), "+f"(D[1]), "+f"(D[2]), "+f"(D[3])                    \
        : "r"(A[0]), "r"(A[1]), "r"(A[2]), "r"(A[3]), "r"(B0), "r"(B1))

__device__ __forceinline__ void cp16(uint32_t s, const void* g) {
    asm volatile("cp.async.cg.shared.global [%0], [%1], 16;" :: "r"(s), "l"(g));
}
__device__ __forceinline__ void cp_commit() { asm volatile("cp.async.commit_group;"); }
__device__ __forceinline__ void cp_wait0()  { asm volatile("cp.async.wait_group 0;"); }

// ---------------------------------------------------------------------------
// Stage A: tmp[bi][c][h] = sum_a z[bi][a] * W1[a*16384 + c*512 + h], emitted
// as fp16 GEMM1 B-fragments (same layout as R11):
//   u32 idx = (bi*16+chk)*512 + ((ntile*2+s)*2+bh)*32 + lane,
//   val = {tmp[c][h], tmp[c+1][h]},  h = chk*32+ntile*8+(lane>>2),
//                                    c = s*16+bh*8+(lane&3)*2.
// ---------------------------------------------------------------------------
__global__ __launch_bounds__(256) void stage_a_kernel(
    const float* __restrict__ z, const float* __restrict__ W1)
{
    __shared__ float zt[64][33];
    __shared__ float wt[32][132];
    const int oct = blockIdx.x & 3;
    const int hg  = blockIdx.x >> 2;
    const int bi0 = blockIdx.y * 64;
    const int c0  = oct * 8, h0 = hg * 16;
    const int tid = threadIdx.x;

    for (int idx = tid; idx < 64 * 32; idx += 256) {
        int r = idx >> 5, a = idx & 31;
        zt[r][a] = z[(bi0 + r) * 32 + a];
    }
    for (int idx = tid; idx < 32 * 128; idx += 256) {
        int a = idx >> 7, col = idx & 127;
        int ci = col >> 4, hi = col & 15;
        wt[a][col] = W1[a * 16384 + (c0 + ci) * 512 + h0 + hi];
    }
    __syncthreads();

    const int tm = tid >> 4;
    const int tn = tid & 15;

    float acc[4][8];
#pragma unroll
    for (int i = 0; i < 4; i++)
#pragma unroll
        for (int j = 0; j < 8; j++) acc[i][j] = 0.f;

#pragma unroll
    for (int k = 0; k < 32; k++) {
        float a[4], bb[8];
#pragma unroll
        for (int i = 0; i < 4; i++) a[i] = zt[tm * 4 + i][k];
#pragma unroll
        for (int j = 0; j < 8; j++) bb[j] = wt[k][j * 16 + tn];
#pragma unroll
        for (int i = 0; i < 4; i++)
#pragma unroll
            for (int j = 0; j < 8; j++) acc[i][j] = fmaf(a[i], bb[j], acc[i][j]);
    }

    const int h   = h0 + tn;
    const int chk = h >> 5;
    const int nt  = (h >> 3) & 3;
    const int g   = h & 7;
    const int s   = oct >> 1, bh = oct & 1;
#pragma unroll
    for (int i = 0; i < 4; i++) {
        const int bi = bi0 + tm * 4 + i;
        uint4 v;
        v.x = ph2(acc[i][0], acc[i][1]);
        v.y = ph2(acc[i][2], acc[i][3]);
        v.z = ph2(acc[i][4], acc[i][5]);
        v.w = ph2(acc[i][6], acc[i][7]);
        ((uint4*)g_tmph)[(size_t)(bi * 16 + chk) * 128 + ((nt * 2 + s) * 2 + bh) * 8 + g] = v;
    }
}

// ---------------------------------------------------------------------------
// Pack W2 -> fp16 GEMM2 B-frags, uint4-tile layout:
//   u32 idx = chk*4096 + nt*128 + lane*4 + s*2 + bh
//   val = {W2[h][k2], W2[h+1][k2]},
//   h = chk*32 + s*16 + bh*8 + (lane&3)*2,  k2 = nt*8 + (lane>>2)
// One uint4 at (nt*128 + lane*4) = all 4 B regs for that nt tile.
// ---------------------------------------------------------------------------
__global__ __launch_bounds__(256) void pack_w2_kernel(const float* __restrict__ W2)
{
    const int gid  = blockIdx.x * 256 + threadIdx.x;   // 65536
    const int bh   = gid & 1;
    const int s    = (gid >> 1) & 1;
    const int lane = (gid >> 2) & 31;
    const int nt   = (gid >> 7) & 31;
    const int chk  = gid >> 12;
    const int h  = chk * 32 + s * 16 + bh * 8 + (lane & 3) * 2;
    const int k2 = nt * 8 + (lane >> 2);
    g_w2h[gid] = ph2(W2[h * 256 + k2], W2[(h + 1) * 256 + k2]);
}

// ---------------------------------------------------------------------------
// Pack z -> fp16 GEMM1 A-frags: u32 idx = (tile*2+s)*128 + lane*4 + r
// ---------------------------------------------------------------------------
__global__ __launch_bounds__(256) void pack_z_kernel(const float* __restrict__ z)
{
    const int gid  = blockIdx.x * 256 + threadIdx.x;   // 16384
    const int r    = gid & 3;
    const int lane = (gid >> 2) & 31;
    const int s    = (gid >> 7) & 1;
    const int tile = gid >> 8;
    const int g = lane >> 2, t = lane & 3;
    const int row = tile * 16 + g + (r & 1) * 8;
    const int col = s * 16 + t * 2 + (r >> 1) * 8;
    g_zh[gid] = ph2(z[row * 32 + col], z[row * 32 + col + 1]);
}

// ---------------------------------------------------------------------------
// Main fused kernel: grid 4096 = (b, i, jt of 4), 128 threads, 3 CTAs/SM.
// Warp w owns j rows [w*16, w*16+16) end-to-end:
//   GEMM1: 16j x 32h chunk (8 MMAs), C-frag -> relu+bias -> fp16 A-frag (regs)
//   GEMM2: 16j x 256k2, one uint4 B load per nt (32 LDS.128), acc2[32][4] fp32.
// smem u32: tmp 2x512 @0, w2 2x4096 @1024; floats: b1@9216 b2@9728 w3@9984.
// ---------------------------------------------------------------------------
#define SM_TOT  10240          // floats = 40960 bytes

__global__ __launch_bounds__(128, 3) void decoder_main_kernel(
    const float* __restrict__ motif,
    const float* __restrict__ b1, const float* __restrict__ b2,
    const float* __restrict__ W3, const float* __restrict__ b3,
    float* __restrict__ out)
{
    extern __shared__ float sm[];
    uint32_t* smu = (uint32_t*)sm;
    const uint32_t s_u32 = (uint32_t)__cvta_generic_to_shared(sm);
    float* s_b1 = sm + 9216;
    float* s_b2 = sm + 9728;
    float* s_w3 = sm + 9984;

    const int cta = blockIdx.x;
    const int jt  = cta & 3;
    const int i   = (cta >> 2) & 255;
    const int b   = cta >> 10;
    const int bi  = b * 256 + i;
    const int j0  = jt * 64;

    const int tid  = threadIdx.x;
    const int w    = tid >> 5;
    const int lane = tid & 31;
    const int g    = lane >> 2;
    const int t    = lane & 3;

    // ---- z A-frags, register-resident (chunk-invariant) ------------------
    uint32_t za[2][4];
    {
        const int tile = ((b * 256 + j0) >> 4) + w;
        const uint4* zf = (const uint4*)g_zh;
#pragma unroll
        for (int s = 0; s < 2; s++) {
            uint4 v = zf[(tile * 2 + s) * 32 + lane];
            za[s][0] = v.x; za[s][1] = v.y; za[s][2] = v.z; za[s][3] = v.w;
        }
    }

    // ---- prologue: async loads of chunk 0 --------------------------------
    {
        const uint4* wsrc = (const uint4*)g_w2h;
#pragma unroll
        for (int r = 0; r < 8; r++)
            cp16(s_u32 + (1024 + (tid + r * 128) * 4) * 4, wsrc + tid + r * 128);
        const uint4* tsrc = (const uint4*)g_tmph + (size_t)bi * 16 * 128;
        cp16(s_u32 + (tid * 4) * 4, tsrc + tid);
        cp_commit();
    }
    for (int idx = tid; idx < 1024; idx += 128) {
        if (idx < 512)       s_b1[idx] = b1[idx];
        else if (idx < 768)  s_b2[idx - 512] = b2[idx - 512];
        else                 s_w3[idx - 768] = W3[idx - 768];
    }

    float acc2[32][4];
#pragma unroll
    for (int nt = 0; nt < 32; nt++)
#pragma unroll
        for (int r = 0; r < 4; r++) acc2[nt][r] = 0.f;

    int buf = 0;
    for (int chk = 0; chk < 16; chk++) {
        cp_wait0();
        __syncthreads();

        if (chk < 15) {
            const int nb = buf ^ 1;
            const uint4* wsrc = (const uint4*)g_w2h + (chk + 1) * 1024;
#pragma unroll
            for (int r = 0; r < 8; r++)
                cp16(s_u32 + (1024 + nb * 4096 + (tid + r * 128) * 4) * 4,
                     wsrc + tid + r * 128);
            const uint4* tsrc = (const uint4*)g_tmph + ((size_t)bi * 16 + chk + 1) * 128;
            cp16(s_u32 + (nb * 512 + tid * 4) * 4, tsrc + tid);
            cp_commit();
        }

        const uint32_t* tb = smu + buf * 512;
        const uint32_t* wb = smu + 1024 + buf * 4096;

        // ---- GEMM1: acc1 = z_rows(w) . tmp^T  (16j x 32h) ----------------
        float acc1[4][4];
#pragma unroll
        for (int nt = 0; nt < 4; nt++)
#pragma unroll
            for (int r = 0; r < 4; r++) acc1[nt][r] = 0.f;

#pragma unroll
        for (int s = 0; s < 2; s++)
#pragma unroll
            for (int nt = 0; nt < 4; nt++) {
                uint32_t b0 = tb[((nt * 2 + s) * 2 + 0) * 32 + lane];
                uint32_t bb = tb[((nt * 2 + s) * 2 + 1) * 32 + lane];
                MMA_F16(acc1[nt], za[s], b0, bb);
            }

        // bias + relu + fp16 pack: C-frag -> A-frag, all in registers
        uint32_t h1h[4][2];
#pragma unroll
        for (int nt = 0; nt < 4; nt++) {
            const float* bb = s_b1 + chk * 32 + nt * 8 + t * 2;
            float v0 = fmaxf(acc1[nt][0] + bb[0], 0.f);
            float v1 = fmaxf(acc1[nt][1] + bb[1], 0.f);
            float v2 = fmaxf(acc1[nt][2] + bb[0], 0.f);
            float v3 = fmaxf(acc1[nt][3] + bb[1], 0.f);
            h1h[nt][0] = ph2(v0, v1);
            h1h[nt][1] = ph2(v2, v3);
        }

        // ---- GEMM2: acc2 += h1(16j) . W2chunk (256 k2) -------------------
        {
            uint32_t A0[4] = { h1h[0][0], h1h[0][1], h1h[1][0], h1h[1][1] };
            uint32_t A1[4] = { h1h[2][0], h1h[2][1], h1h[3][0], h1h[3][1] };
#pragma unroll
            for (int nt = 0; nt < 32; nt++) {
                uint4 bv = *(const uint4*)&wb[nt * 128 + lane * 4];
                MMA_F16(acc2[nt], A0, bv.x, bv.y);
                MMA_F16(acc2[nt], A1, bv.z, bv.w);
            }
        }
        buf ^= 1;
    }

    // ---- epilogue: relu(+b2) . W3 (full k2 in-warp), quad-reduce ---------
    float ps0 = 0.f, ps1 = 0.f;
#pragma unroll
    for (int nt = 0; nt < 32; nt++) {
        const int k = nt * 8 + t * 2;
        float h2a = fmaxf(acc2[nt][0] + s_b2[k],     0.f);
        float h2b = fmaxf(acc2[nt][1] + s_b2[k + 1], 0.f);
        float h2c = fmaxf(acc2[nt][2] + s_b2[k],     0.f);
        float h2d = fmaxf(acc2[nt][3] + s_b2[k + 1], 0.f);
        ps0 = fmaf(h2a, s_w3[k], ps0);  ps0 = fmaf(h2b, s_w3[k + 1], ps0);
        ps1 = fmaf(h2c, s_w3[k], ps1);  ps1 = fmaf(h2d, s_w3[k + 1], ps1);
    }
    ps0 += __shfl_xor_sync(0xffffffffu, ps0, 1);
    ps0 += __shfl_xor_sync(0xffffffffu, ps0, 2);
    ps1 += __shfl_xor_sync(0xffffffffu, ps1, 1);
    ps1 += __shfl_xor_sync(0xffffffffu, ps1, 2);

    if (t == 0) {
        const float b3v = b3[0];
        const float mi  = motif[b * 256 + i];
#pragma unroll
        for (int u = 0; u < 2; u++) {
            const int j = j0 + w * 16 + g + u * 8;
            float logit = ((u ? ps1 : ps0) + b3v) * (mi * motif[b * 256 + j]);
            float cmap  = 1.f / (1.f + __expf(-logit));
            size_t base = (size_t)bi * 256 + j;
            out[base]       = cmap;
            out[BNN + base] = logit;
        }
    }
}

// ---------------------------------------------------------------------------
extern "C" void kernel_launch(void* const* d_in, const int* in_sizes, int n_in,
                              void* d_out, int out_size)
{
    const float* z     = (const float*)d_in[0];
    const float* motif = (const float*)d_in[1];
    const float* W1    = (const float*)d_in[3];
    const float* b1    = (const float*)d_in[4];
    const float* W2    = (const float*)d_in[5];
    const float* b2    = (const float*)d_in[6];
    const float* W3    = (const float*)d_in[7];
    const float* b3    = (const float*)d_in[8];
    float* out = (float*)d_out;

    (void)in_sizes; (void)n_in; (void)out_size;

    cudaFuncSetAttribute(decoder_main_kernel,
                         cudaFuncAttributeMaxDynamicSharedMemorySize,
                         SM_TOT * (int)sizeof(float));

    stage_a_kernel<<<dim3(128, 16), 256>>>(z, W1);
    pack_w2_kernel<<<256, 256>>>(W2);
    pack_z_kernel<<<64, 256>>>(z);
    decoder_main_kernel<<<4096, 128, SM_TOT * sizeof(float)>>>(
        motif, b1, b2, W3, b3, out);
}